// round 1
// baseline (speedup 1.0000x reference)
#include <cuda_runtime.h>
#include <math.h>

// Problem constants
#define BB 2
#define SS 4096
#define DD 768
#define HH 12
#define GG 64
#define HD 64
#define WW 256
#define NCC 16
#define NHEADS_S ((size_t)BB * HH * SS * HD)   // 6291456

// ---------------- scratch (static device globals; no allocation) ----------------
__device__ float g_xbuf [(size_t)BB * SS * DD];     // x row-major (B,S,D)
__device__ float g_q    [NHEADS_S];                 // [b][h][s][hd], scaled
__device__ float g_k    [NHEADS_S];
__device__ float g_v    [NHEADS_S];
__device__ float g_kg   [NHEADS_S];
__device__ float g_vg   [NHEADS_S];
__device__ float g_qg   [(size_t)BB * HH * GG * HD];// [b][h][g][hd], scaled
__device__ float g_attn [NHEADS_S];                 // attention out, head layout
__device__ float g_xattn[(size_t)BB * SS * DD];     // attention out, row-major
__device__ float g_pm   [(size_t)BB * HH * GG * 64];          // global-attn partial max
__device__ float g_pl   [(size_t)BB * HH * GG * 64];          // partial sum
__device__ float g_pacc [(size_t)BB * HH * GG * 64 * HD];     // partial acc

// ---------------- transpose: query (S,B,D) -> xbuf (B,S,D) ----------------
__global__ void k_xin(const float* __restrict__ query) {
    size_t t = (size_t)blockIdx.x * blockDim.x + threadIdx.x;
    if (t >= (size_t)BB * SS * DD) return;
    int d  = (int)(t % DD);
    size_t rs = t / DD;
    int b = (int)(rs >> 12);
    int s = (int)(rs & 4095);
    g_xbuf[t] = query[((size_t)s * BB + b) * DD + d];
}

// ---------------- transpose: attn head layout -> row-major (B,S,D) ----------------
__global__ void k_xattn(void) {
    size_t t = (size_t)blockIdx.x * blockDim.x + threadIdx.x;
    if (t >= (size_t)BB * SS * DD) return;
    int d  = (int)(t % DD);
    size_t rs = t / DD;
    int b = (int)(rs >> 12);
    int s = (int)(rs & 4095);
    int h = d >> 6, hd = d & 63;
    g_xattn[t] = g_attn[(((size_t)b * HH + h) * SS + s) * 64 + hd];
}

// ---------------- fp32 SGEMM: C(Mx768) = X(Mx768) @ W(768x768) + bias ----------------
// in_mode : 0 -> row r at X + r*768     1 -> qg: r=(b*64+g), row at X + (b*4096+g)*768
// out_mode: 0 -> head layout [b][h][s][hd]   1 -> d_out[(s*B+b)*768+n]   2 -> qg compact
__global__ __launch_bounds__(256, 2)
void sgemm_kernel(const float* __restrict__ X, const float* __restrict__ Wm,
                  const float* __restrict__ bias, float* __restrict__ Out,
                  int in_mode, int out_mode, float scale)
{
    __shared__ float As[8][128];
    __shared__ float Bs[8][128];
    const int tid = threadIdx.x;
    const int m0 = blockIdx.y * 128;
    const int n0 = blockIdx.x * 128;

    const int a_row = tid >> 1;
    const int a_col = (tid & 1) * 4;
    const int b_row = tid >> 5;
    const int b_col = (tid & 31) * 4;

    const int r_a = m0 + a_row;
    const float* xrow;
    if (in_mode == 0) {
        xrow = X + (size_t)r_a * 768;
    } else {
        int bb = r_a >> 6, gg2 = r_a & 63;
        xrow = X + ((size_t)bb * 4096 + gg2) * 768;
    }

    const int rowbase = (tid >> 4) * 8;
    const int colbase = (tid & 15) * 8;

    float acc[8][8];
#pragma unroll
    for (int i = 0; i < 8; i++)
#pragma unroll
        for (int j = 0; j < 8; j++) acc[i][j] = 0.f;

    for (int k0 = 0; k0 < 768; k0 += 8) {
        float4 av = *(const float4*)(xrow + k0 + a_col);
        float4 bv = *(const float4*)(Wm + (size_t)(k0 + b_row) * 768 + n0 + b_col);
        __syncthreads();
        As[a_col + 0][a_row] = av.x;
        As[a_col + 1][a_row] = av.y;
        As[a_col + 2][a_row] = av.z;
        As[a_col + 3][a_row] = av.w;
        *(float4*)&Bs[b_row][b_col] = bv;
        __syncthreads();
#pragma unroll
        for (int kk = 0; kk < 8; kk++) {
            float4 a0 = *(const float4*)&As[kk][rowbase];
            float4 a1 = *(const float4*)&As[kk][rowbase + 4];
            float4 b0 = *(const float4*)&Bs[kk][colbase];
            float4 b1 = *(const float4*)&Bs[kk][colbase + 4];
            float ra[8] = {a0.x, a0.y, a0.z, a0.w, a1.x, a1.y, a1.z, a1.w};
            float rb[8] = {b0.x, b0.y, b0.z, b0.w, b1.x, b1.y, b1.z, b1.w};
#pragma unroll
            for (int i = 0; i < 8; i++)
#pragma unroll
                for (int j = 0; j < 8; j++)
                    acc[i][j] += ra[i] * rb[j];
        }
    }

#pragma unroll
    for (int i = 0; i < 8; i++) {
        int rr = m0 + rowbase + i;
#pragma unroll
        for (int j = 0; j < 8; j++) {
            int nn = n0 + colbase + j;
            float val = (acc[i][j] + bias[nn]) * scale;
            if (out_mode == 0) {
                int bb = rr >> 12, ss = rr & 4095;
                int hh = nn >> 6, hd = nn & 63;
                Out[(((size_t)bb * HH + hh) * SS + ss) * 64 + hd] = val;
            } else if (out_mode == 1) {
                int bb = rr >> 12, ss = rr & 4095;
                Out[((size_t)ss * BB + bb) * DD + nn] = val;
            } else {
                int bb = rr >> 6, gg2 = rr & 63;
                int hh = nn >> 6, hd = nn & 63;
                Out[(((size_t)bb * HH + hh) * GG + gg2) * 64 + hd] = val;
            }
        }
    }
}

// ---------------- local windowed attention (+ global columns) ----------------
// grid (NC, H, B), 256 threads = 256 q rows per chunk. Online softmax over
// 13 key tiles of 64: tile 0 = global keys (positions 0..63, never masked),
// tiles 1..12 = local band positions (c-1)*256 + (t-1)*64 + jj.
__global__ __launch_bounds__(256, 1)
void local_attn_kernel(const int* __restrict__ mask)
{
    const int c = blockIdx.x, h = blockIdx.y, b = blockIdx.z;
    const int i = threadIdx.x;            // row within chunk
    const int s = c * WW + i;
    const size_t bh = (size_t)b * HH + h;

    const float* qrow = g_q + (bh * SS + s) * 64;
    float qr[64];
#pragma unroll
    for (int d = 0; d < 64; d += 4) {
        float4 t4 = *(const float4*)(qrow + d);
        qr[d] = t4.x; qr[d+1] = t4.y; qr[d+2] = t4.z; qr[d+3] = t4.w;
    }

    float acc[64];
#pragma unroll
    for (int d = 0; d < 64; d++) acc[d] = 0.f;
    float mrun = -1e30f, lrun = 0.f;

    __shared__ float ks[64][68];
    __shared__ float vs[64][68];
    __shared__ int   okf[64];

    const float* kbase = g_k + bh * SS * 64;
    const float* vbase = g_v + bh * SS * 64;

    for (int t = 0; t < 13; t++) {
        const int pbase = (t == 0) ? 0 : (c - 1) * WW + (t - 1) * 64;

        __syncthreads();
        {
            int row  = threadIdx.x >> 2;
            int col0 = (threadIdx.x & 3) * 16;
            int p = pbase + row;
            bool inr = (p >= 0 && p < SS);
            const float* kr = kbase + (size_t)(inr ? p : 0) * 64;
            const float* vr = vbase + (size_t)(inr ? p : 0) * 64;
#pragma unroll
            for (int e = 0; e < 16; e += 4) {
                float4 kv = inr ? *(const float4*)(kr + col0 + e) : make_float4(0,0,0,0);
                float4 vv = inr ? *(const float4*)(vr + col0 + e) : make_float4(0,0,0,0);
                *(float4*)&ks[row][col0 + e] = kv;
                *(float4*)&vs[row][col0 + e] = vv;
            }
            if ((threadIdx.x & 3) == 0) {
                bool okp;
                if (t == 0) okp = true;                         // gsc columns: unmasked
                else        okp = inr && (mask[b * SS + p] == 0); // local: not pad/global
                okf[row] = okp ? 1 : 0;
            }
        }
        __syncthreads();

        const int jtile0 = (t - 1) * 64;
#pragma unroll
        for (int half = 0; half < 2; half++) {
            float sc[32];
            float mc = -1e30f;
#pragma unroll
            for (int jj = 0; jj < 32; jj++) {
                const int j2 = half * 32 + jj;
                float ssum = 0.f;
#pragma unroll
                for (int d = 0; d < 64; d += 4) {
                    float4 k4 = *(const float4*)&ks[j2][d];
                    ssum += qr[d] * k4.x + qr[d+1] * k4.y + qr[d+2] * k4.z + qr[d+3] * k4.w;
                }
                bool ok;
                if (t == 0) ok = true;
                else {
                    int j = jtile0 + j2;       // 0..767
                    ok = (j >= i) && (j <= i + 2 * WW) && (okf[j2] != 0);
                }
                sc[jj] = ok ? ssum : -1e30f;
                mc = fmaxf(mc, sc[jj]);
            }
            float mnew = fmaxf(mrun, mc);
            float corr = __expf(mrun - mnew);
            lrun *= corr;
#pragma unroll
            for (int d = 0; d < 64; d++) acc[d] *= corr;
            float psum = 0.f;
#pragma unroll
            for (int jj = 0; jj < 32; jj++) {
                float pp = __expf(sc[jj] - mnew);
                sc[jj] = pp;
                psum += pp;
            }
            lrun += psum;
            mrun = mnew;
#pragma unroll
            for (int jj = 0; jj < 32; jj++) {
                const int j2 = half * 32 + jj;
                const float pv = sc[jj];
#pragma unroll
                for (int d = 0; d < 64; d += 4) {
                    float4 v4 = *(const float4*)&vs[j2][d];
                    acc[d]   += pv * v4.x;
                    acc[d+1] += pv * v4.y;
                    acc[d+2] += pv * v4.z;
                    acc[d+3] += pv * v4.w;
                }
            }
        }
    }

    const float inv = 1.f / lrun;
    float* orow = g_attn + (bh * SS + s) * 64;
#pragma unroll
    for (int d = 0; d < 64; d += 4) {
        float4 o4 = make_float4(acc[d]*inv, acc[d+1]*inv, acc[d+2]*inv, acc[d+3]*inv);
        *(float4*)(orow + d) = o4;
    }
}

// ---------------- global attention (rows g < G), split-K partials ----------------
// grid (16 splits, H, B), 256 threads: thread = (g = tid&63, part = tid>>6).
// Each thread covers 64 keys; 64 partials per row combined by the next kernel.
__global__ __launch_bounds__(256, 1)
void gattn_part_kernel(const int* __restrict__ mask)
{
    const int split = blockIdx.x, h = blockIdx.y, b = blockIdx.z;
    const int g    = threadIdx.x & 63;
    const int part = threadIdx.x >> 6;
    const size_t bh = (size_t)b * HH + h;

    const float* qrow = g_qg + (bh * GG + g) * 64;
    float qr[64];
#pragma unroll
    for (int d = 0; d < 64; d += 4) {
        float4 t4 = *(const float4*)(qrow + d);
        qr[d] = t4.x; qr[d+1] = t4.y; qr[d+2] = t4.z; qr[d+3] = t4.w;
    }

    float acc[64];
#pragma unroll
    for (int d = 0; d < 64; d++) acc[d] = 0.f;
    float m = -1e30f, l = 0.f;

    const int p0 = split * 256 + part * 64;
    const float* kbase = g_kg + bh * SS * 64;
    const float* vbase = g_vg + bh * SS * 64;
    const int* mrow = mask + (size_t)b * SS;

    for (int kk = 0; kk < 64; kk++) {
        const int p = p0 + kk;
        const float* kr = kbase + (size_t)p * 64;
        float ssum = 0.f;
#pragma unroll
        for (int d = 0; d < 64; d += 4) {
            float4 k4 = *(const float4*)(kr + d);
            ssum += qr[d] * k4.x + qr[d+1] * k4.y + qr[d+2] * k4.z + qr[d+3] * k4.w;
        }
        if (mrow[p] > 0) ssum = -1e30f;      // is_pad
        float mnew = fmaxf(m, ssum);
        float corr = __expf(m - mnew);
        float pp   = __expf(ssum - mnew);
        l = l * corr + pp;
        const float* vr = vbase + (size_t)p * 64;
#pragma unroll
        for (int d = 0; d < 64; d += 4) {
            float4 v4 = *(const float4*)(vr + d);
            acc[d]   = acc[d]   * corr + pp * v4.x;
            acc[d+1] = acc[d+1] * corr + pp * v4.y;
            acc[d+2] = acc[d+2] * corr + pp * v4.z;
            acc[d+3] = acc[d+3] * corr + pp * v4.w;
        }
        m = mnew;
    }

    const size_t idx = (bh * GG + g) * 64 + (split * 4 + part);
    g_pm[idx] = m;
    g_pl[idx] = l;
    float* ap = g_pacc + idx * 64;
#pragma unroll
    for (int d = 0; d < 64; d += 4) {
        *(float4*)(ap + d) = make_float4(acc[d], acc[d+1], acc[d+2], acc[d+3]);
    }
}

// combine 64 partials per global row, overwrite g_attn rows s<G
__global__ void gattn_combine_kernel(void)
{
    const int rid = blockIdx.x * blockDim.x + threadIdx.x;   // 0..1535
    if (rid >= BB * HH * GG) return;
    float M = -1e30f;
    for (int p = 0; p < 64; p++) M = fmaxf(M, g_pm[(size_t)rid * 64 + p]);
    float L = 0.f;
    float acc[64];
#pragma unroll
    for (int d = 0; d < 64; d++) acc[d] = 0.f;
    for (int p = 0; p < 64; p++) {
        const float w = __expf(g_pm[(size_t)rid * 64 + p] - M);
        L += g_pl[(size_t)rid * 64 + p] * w;
        const float* ap = g_pacc + ((size_t)rid * 64 + p) * 64;
#pragma unroll
        for (int d = 0; d < 64; d += 4) {
            float4 a4 = *(const float4*)(ap + d);
            acc[d]   += w * a4.x;
            acc[d+1] += w * a4.y;
            acc[d+2] += w * a4.z;
            acc[d+3] += w * a4.w;
        }
    }
    const float inv = 1.f / L;
    const int bh = rid >> 6, g = rid & 63;
    float* orow = g_attn + ((size_t)bh * SS + g) * 64;
#pragma unroll
    for (int d = 0; d < 64; d += 4) {
        *(float4*)(orow + d) = make_float4(acc[d]*inv, acc[d+1]*inv, acc[d+2]*inv, acc[d+3]*inv);
    }
}

// ---------------- launcher ----------------
extern "C" void kernel_launch(void* const* d_in, const int* in_sizes, int n_in,
                              void* d_out, int out_size)
{
    (void)in_sizes; (void)n_in; (void)out_size;
    const float* query = (const float*)d_in[0];
    const int*   mask  = (const int*)d_in[1];
    const float* Wq  = (const float*)d_in[2];
    const float* bq  = (const float*)d_in[3];
    const float* Wk  = (const float*)d_in[4];
    const float* bk  = (const float*)d_in[5];
    const float* Wv  = (const float*)d_in[6];
    const float* bv  = (const float*)d_in[7];
    const float* Wqg = (const float*)d_in[8];
    const float* bqg = (const float*)d_in[9];
    const float* Wkg = (const float*)d_in[10];
    const float* bkg = (const float*)d_in[11];
    const float* Wvg = (const float*)d_in[12];
    const float* bvg = (const float*)d_in[13];
    const float* Wo  = (const float*)d_in[14];
    const float* bo  = (const float*)d_in[15];
    float* out = (float*)d_out;

    float *xbuf, *qb, *kb, *vb, *kgb, *vgb, *qgb, *xat;
    cudaGetSymbolAddress((void**)&xbuf, g_xbuf);
    cudaGetSymbolAddress((void**)&qb,   g_q);
    cudaGetSymbolAddress((void**)&kb,   g_k);
    cudaGetSymbolAddress((void**)&vb,   g_v);
    cudaGetSymbolAddress((void**)&kgb,  g_kg);
    cudaGetSymbolAddress((void**)&vgb,  g_vg);
    cudaGetSymbolAddress((void**)&qgb,  g_qg);
    cudaGetSymbolAddress((void**)&xat,  g_xattn);

    const int ntot = BB * SS * DD;
    k_xin<<<(ntot + 255) / 256, 256>>>(query);

    dim3 gemmgrid(DD / 128, (BB * SS) / 128);   // (6, 64)
    sgemm_kernel<<<gemmgrid, 256>>>(xbuf, Wq,  bq,  qb,  0, 0, 0.125f);
    sgemm_kernel<<<gemmgrid, 256>>>(xbuf, Wk,  bk,  kb,  0, 0, 1.0f);
    sgemm_kernel<<<gemmgrid, 256>>>(xbuf, Wv,  bv,  vb,  0, 0, 1.0f);
    sgemm_kernel<<<gemmgrid, 256>>>(xbuf, Wkg, bkg, kgb, 0, 0, 1.0f);
    sgemm_kernel<<<gemmgrid, 256>>>(xbuf, Wvg, bvg, vgb, 0, 0, 1.0f);
    sgemm_kernel<<<dim3(DD / 128, 1), 256>>>(xbuf, Wqg, bqg, qgb, 1, 2, 0.125f);

    local_attn_kernel<<<dim3(NCC, HH, BB), 256>>>(mask);
    gattn_part_kernel<<<dim3(16, HH, BB), 256>>>(mask);
    gattn_combine_kernel<<<(BB * HH * GG + 255) / 256, 256>>>();

    k_xattn<<<(ntot + 255) / 256, 256>>>();
    sgemm_kernel<<<gemmgrid, 256>>>(xat, Wo, bo, out, 0, 1, 1.0f);
}

// round 3
// speedup vs baseline: 1.9044x; 1.9044x over previous
#include <cuda_runtime.h>
#include <math.h>
#include <cstdint>

// Problem constants
#define BB 2
#define SS 4096
#define DD 768
#define HH 12
#define GG 64
#define HD 64
#define WW 256
#define NCC 16
#define NHEADS_S ((size_t)BB * HH * SS * HD)   // 6291456

// ---------------- scratch (static device globals; no allocation) ----------------
__device__ float g_xbuf [(size_t)BB * SS * DD];     // x row-major (B,S,D), tf32-rounded
__device__ float g_wt   [7][(size_t)DD * DD];       // W^T per weight, tf32-rounded
__device__ float g_q    [NHEADS_S];                 // [b][h][s][hd], scaled
__device__ float g_k    [NHEADS_S];
__device__ float g_v    [NHEADS_S];
__device__ float g_kg   [NHEADS_S];
__device__ float g_vg   [NHEADS_S];
__device__ float g_qg   [(size_t)BB * HH * GG * HD];
__device__ float g_attn [NHEADS_S];                 // attention out, head layout
__device__ float g_xattn[(size_t)BB * SS * DD];     // attention out, row-major, tf32-rounded
__device__ float g_pm   [(size_t)BB * HH * GG * 64];
__device__ float g_pl   [(size_t)BB * HH * GG * 64];
__device__ float g_pacc [(size_t)BB * HH * GG * 64 * HD];

// ---------------- helpers ----------------
__device__ __forceinline__ uint32_t smem_u32(const void* p) {
    uint32_t a;
    asm("{ .reg .u64 t; cvta.to.shared.u64 t, %1; cvt.u32.u64 %0, t; }" : "=r"(a) : "l"(p));
    return a;
}
__device__ __forceinline__ float to_tf32(float v) {
    float r;
    asm("cvt.rn.tf32.f32 %0, %1;" : "=f"(r) : "f"(v));
    return r;
}
#define CP_ASYNC16(saddr, gptr) \
    asm volatile("cp.async.cg.shared.global [%0], [%1], 16;" :: "r"(saddr), "l"(gptr))
#define CP_COMMIT() asm volatile("cp.async.commit_group;" ::: "memory")
#define CP_WAIT(N)  asm volatile("cp.async.wait_group %0;" :: "n"(N) : "memory")

// m16n8k8 tf32 mma (sm_80+ portable; runs as HMMA on sm_103 tensor pipe)
#define MMA_TF32(d, a, b) \
    asm volatile( \
        "mma.sync.aligned.m16n8k8.row.col.f32.tf32.tf32.f32 " \
        "{%0,%1,%2,%3}, {%4,%5,%6,%7}, {%8,%9}, {%0,%1,%2,%3};" \
        : "+f"((d)[0]), "+f"((d)[1]), "+f"((d)[2]), "+f"((d)[3]) \
        : "r"((a)[0]), "r"((a)[1]), "r"((a)[2]), "r"((a)[3]), \
          "r"((b)[0]), "r"((b)[1]))

// ---------------- transpose: query (S,B,D) -> xbuf (B,S,D), tf32-rounded ----------------
__global__ void k_xin(const float* __restrict__ query) {
    size_t t = (size_t)blockIdx.x * blockDim.x + threadIdx.x;
    if (t >= (size_t)BB * SS * DD) return;
    int d  = (int)(t % DD);
    size_t rs = t / DD;
    int b = (int)(rs >> 12);
    int s = (int)(rs & 4095);
    g_xbuf[t] = to_tf32(query[((size_t)s * BB + b) * DD + d]);
}

// ---------------- transpose: attn head layout -> row-major (B,S,D), tf32-rounded ----------------
__global__ void k_xattn(void) {
    size_t t = (size_t)blockIdx.x * blockDim.x + threadIdx.x;
    if (t >= (size_t)BB * SS * DD) return;
    int d  = (int)(t % DD);
    size_t rs = t / DD;
    int b = (int)(rs >> 12);
    int s = (int)(rs & 4095);
    int h = d >> 6, hd = d & 63;
    g_xattn[t] = to_tf32(g_attn[(((size_t)b * HH + h) * SS + s) * 64 + hd]);
}

// ---------------- weight transpose: WT[n][k] = rn_tf32(W[k][n]) ----------------
__global__ void k_wt(const float* __restrict__ W, float* __restrict__ WT) {
    __shared__ float tile[32][33];
    int x = blockIdx.x * 32 + threadIdx.x;   // n
    int y0 = blockIdx.y * 32;                // k base
#pragma unroll
    for (int j = 0; j < 32; j += 8)
        tile[threadIdx.y + j][threadIdx.x] = W[(size_t)(y0 + threadIdx.y + j) * DD + x];
    __syncthreads();
    int kx = y0 + threadIdx.x;               // k
#pragma unroll
    for (int j = 0; j < 32; j += 8) {
        int n = blockIdx.x * 32 + threadIdx.y + j;
        WT[(size_t)n * DD + kx] = to_tf32(tile[threadIdx.x][threadIdx.y + j]);
    }
}

// ---------------- tf32 mma.sync GEMM: C(Mx768) = X(Mx768) @ WT^T + bias ----------------
// CTA tile 128x128, 256 threads = 8 warps as 2(m) x 4(n), warp tile 64x32.
// K=768 in 24 chunks of 32, cp.async double-buffered.
// smem per operand per stage: 128 rows x stride 36 floats (bank-conflict-free frags).
// in_mode : 0 -> row r at X + r*768     1 -> qg gather: row at X + ((r>>6)*4096 + (r&63))*768
// out_mode: 0 -> head layout [b][h][s][hd]   1 -> d_out[(s*B+b)*768+n]   2 -> qg compact
#define ASTRIDE 36
#define OPBYTES (128 * ASTRIDE * 4)            // 18432
#define STAGEBYTES (2 * OPBYTES)               // 36864
#define SM_TOTAL (2 * STAGEBYTES)              // 73728

__global__ __launch_bounds__(256, 2)
void mma_gemm(const float* __restrict__ X, const float* __restrict__ WT,
              const float* __restrict__ bias, float* __restrict__ Out,
              int in_mode, int out_mode, float scale)
{
    extern __shared__ char smem[];
    const uint32_t sbase = smem_u32(smem);
    const int tid = threadIdx.x;
    const int wid = tid >> 5, lane = tid & 31;
    const int wm = (wid >> 2) * 64;            // warp m offset in tile
    const int wn = (wid & 3) * 32;             // warp n offset in tile
    const int lr = lane >> 2;                  // 0..7
    const int lc = lane & 3;                   // 0..3
    const int m0 = blockIdx.y * 128;
    const int n0 = blockIdx.x * 128;

    // per-thread cp.async assignment: 4 x 16B per operand per chunk
    const float* arow[4];
    const float* brow[4];
    uint32_t dsto[4];
#pragma unroll
    for (int i = 0; i < 4; i++) {
        int li = i * 256 + tid;
        int row = li >> 3, col4 = li & 7;
        int gr = m0 + row;
        int grow = (in_mode == 0) ? gr : ((gr >> 6) * 4096 + (gr & 63));
        arow[i] = X  + (size_t)grow * 768 + col4 * 4;
        brow[i] = WT + (size_t)(n0 + row) * 768 + col4 * 4;
        dsto[i] = (uint32_t)(row * (ASTRIDE * 4) + col4 * 16);
    }

    float acc[4][4][4];
#pragma unroll
    for (int mt = 0; mt < 4; mt++)
#pragma unroll
        for (int nt = 0; nt < 4; nt++)
#pragma unroll
            for (int e = 0; e < 4; e++) acc[mt][nt][e] = 0.f;

    // prologue: chunk 0 -> stage 0
    {
        uint32_t sa = sbase, sb = sbase + OPBYTES;
#pragma unroll
        for (int i = 0; i < 4; i++) {
            CP_ASYNC16(sa + dsto[i], arow[i]);
            CP_ASYNC16(sb + dsto[i], brow[i]);
        }
        CP_COMMIT();
    }

    for (int c = 0; c < 24; c++) {
        if (c < 23) {
            const int k0n = (c + 1) * 32;
            const uint32_t st = ((c + 1) & 1) * STAGEBYTES;
            uint32_t sa = sbase + st, sb = sbase + st + OPBYTES;
#pragma unroll
            for (int i = 0; i < 4; i++) {
                CP_ASYNC16(sa + dsto[i], arow[i] + k0n);
                CP_ASYNC16(sb + dsto[i], brow[i] + k0n);
            }
            CP_COMMIT();
            CP_WAIT(1);
        } else {
            CP_WAIT(0);
        }
        __syncthreads();

        const uint32_t st = (c & 1) * STAGEBYTES;
        const uint32_t* As = (const uint32_t*)(smem + st);
        const uint32_t* Bs = (const uint32_t*)(smem + st + OPBYTES);

#pragma unroll
        for (int ks = 0; ks < 4; ks++) {
            const int k0 = ks * 8;
            uint32_t af[4][4];
#pragma unroll
            for (int mt = 0; mt < 4; mt++) {
                int r0 = wm + mt * 16 + lr;
                af[mt][0] = As[(r0)     * ASTRIDE + k0 + lc];
                af[mt][1] = As[(r0 + 8) * ASTRIDE + k0 + lc];
                af[mt][2] = As[(r0)     * ASTRIDE + k0 + 4 + lc];
                af[mt][3] = As[(r0 + 8) * ASTRIDE + k0 + 4 + lc];
            }
            uint32_t bf[4][2];
#pragma unroll
            for (int nt = 0; nt < 4; nt++) {
                int nrow = wn + nt * 8 + lr;
                bf[nt][0] = Bs[nrow * ASTRIDE + k0 + lc];
                bf[nt][1] = Bs[nrow * ASTRIDE + k0 + 4 + lc];
            }
#pragma unroll
            for (int mt = 0; mt < 4; mt++)
#pragma unroll
                for (int nt = 0; nt < 4; nt++)
                    MMA_TF32(acc[mt][nt], af[mt], bf[nt]);
        }
        __syncthreads();
    }

    // epilogue: C frag (row = wm+mt*16+lr [+8], col = wn+nt*8+lc*2 [+1])
#pragma unroll
    for (int mt = 0; mt < 4; mt++) {
#pragma unroll
        for (int half = 0; half < 2; half++) {
            const int rr = m0 + wm + mt * 16 + lr + half * 8;
#pragma unroll
            for (int nt = 0; nt < 4; nt++) {
                const int nn = n0 + wn + nt * 8 + lc * 2;
                float v0 = (acc[mt][nt][half * 2 + 0] + bias[nn])     * scale;
                float v1 = (acc[mt][nt][half * 2 + 1] + bias[nn + 1]) * scale;
                float* ptr;
                if (out_mode == 0) {
                    int bb = rr >> 12, ss = rr & 4095;
                    int h = nn >> 6, hd0 = nn & 63;
                    ptr = Out + ((((size_t)bb * HH + h) * SS + ss) * 64 + hd0);
                } else if (out_mode == 1) {
                    int bb = rr >> 12, ss = rr & 4095;
                    ptr = Out + ((size_t)ss * BB + bb) * DD + nn;
                } else {
                    int bb = rr >> 6, gg2 = rr & 63;
                    int h = nn >> 6, hd0 = nn & 63;
                    ptr = Out + ((((size_t)bb * HH + h) * GG + gg2) * 64 + hd0);
                }
                *(float2*)ptr = make_float2(v0, v1);
            }
        }
    }
}

// ---------------- local windowed attention (+ global columns) ----------------
// grid (NC*2, H, B), 256 threads: 128 q rows per CTA, 2 threads per row splitting HD.
// row i = rhalf*128 + (tid>>1), half = tid&1 handles dims [half*32, half*32+32).
// Tiles: t=0 global keys (0..63), t=1..12 local band; per-CTA band skip of 2 tiles.
__global__ __launch_bounds__(256, 2)
void local_attn_kernel(const int* __restrict__ mask)
{
    const int c = blockIdx.x >> 1, h = blockIdx.y, b = blockIdx.z;
    const int rhalf = blockIdx.x & 1;
    const int i = rhalf * 128 + (threadIdx.x >> 1);   // row within chunk 0..255
    const int half = threadIdx.x & 1;
    const int s = c * WW + i;
    const size_t bh = (size_t)b * HH + h;

    const float* qrow = g_q + (bh * SS + s) * 64 + half * 32;
    float qr[32];
#pragma unroll
    for (int d = 0; d < 32; d += 4) {
        float4 t4 = *(const float4*)(qrow + d);
        qr[d] = t4.x; qr[d+1] = t4.y; qr[d+2] = t4.z; qr[d+3] = t4.w;
    }

    float acc[32];
#pragma unroll
    for (int d = 0; d < 32; d++) acc[d] = 0.f;
    float mrun = -1e30f, lrun = 0.f;

    __shared__ float ks[64][68];
    __shared__ float vs[64][68];
    __shared__ int   okf[64];

    const float* kbase = g_k + bh * SS * 64;
    const float* vbase = g_v + bh * SS * 64;
    const int r0 = rhalf * 128;              // row range [r0, r0+127]

    for (int t = 0; t < 13; t++) {
        if (t >= 1) {
            const int jlo = (t - 1) * 64;
            // band for rows [r0, r0+127]: j in [r0, r0+127+512]
            if (jlo + 63 < r0 || jlo > r0 + 127 + 2 * WW) continue;
        }
        const int pbase = (t == 0) ? 0 : (c - 1) * WW + (t - 1) * 64;

        __syncthreads();
        {
            int row  = threadIdx.x >> 2;           // 0..63
            int col0 = (threadIdx.x & 3) * 16;
            int p = pbase + row;
            bool inr = (p >= 0 && p < SS);
            const float* kr = kbase + (size_t)(inr ? p : 0) * 64;
            const float* vr = vbase + (size_t)(inr ? p : 0) * 64;
#pragma unroll
            for (int e = 0; e < 16; e += 4) {
                float4 kv = inr ? *(const float4*)(kr + col0 + e) : make_float4(0,0,0,0);
                float4 vv = inr ? *(const float4*)(vr + col0 + e) : make_float4(0,0,0,0);
                *(float4*)&ks[row][col0 + e] = kv;
                *(float4*)&vs[row][col0 + e] = vv;
            }
            if ((threadIdx.x & 3) == 0) {
                bool okp;
                if (t == 0) okp = true;
                else        okp = inr && (mask[b * SS + p] == 0);
                okf[row] = okp ? 1 : 0;
            }
        }
        __syncthreads();

        const int jtile0 = (t - 1) * 64;
#pragma unroll
        for (int hc = 0; hc < 2; hc++) {
            float sc[32];
            float mc = -1e30f;
#pragma unroll
            for (int jj = 0; jj < 32; jj++) {
                const int j2 = hc * 32 + jj;
                float ssum = 0.f;
#pragma unroll
                for (int d = 0; d < 32; d += 4) {
                    float4 k4 = *(const float4*)&ks[j2][half * 32 + d];
                    ssum += qr[d] * k4.x + qr[d+1] * k4.y + qr[d+2] * k4.z + qr[d+3] * k4.w;
                }
                ssum += __shfl_xor_sync(0xffffffffu, ssum, 1);
                bool ok;
                if (t == 0) ok = true;
                else {
                    int j = jtile0 + j2;
                    ok = (j >= i) && (j <= i + 2 * WW) && (okf[j2] != 0);
                }
                sc[jj] = ok ? ssum : -1e30f;
                mc = fmaxf(mc, sc[jj]);
            }
            float mnew = fmaxf(mrun, mc);
            float corr = __expf(mrun - mnew);
            lrun *= corr;
#pragma unroll
            for (int d = 0; d < 32; d++) acc[d] *= corr;
            float psum = 0.f;
#pragma unroll
            for (int jj = 0; jj < 32; jj++) {
                float pp = __expf(sc[jj] - mnew);
                sc[jj] = pp;
                psum += pp;
            }
            lrun += psum;
            mrun = mnew;
#pragma unroll
            for (int jj = 0; jj < 32; jj++) {
                const int j2 = hc * 32 + jj;
                const float pv = sc[jj];
#pragma unroll
                for (int d = 0; d < 32; d += 4) {
                    float4 v4 = *(const float4*)&vs[j2][half * 32 + d];
                    acc[d]   += pv * v4.x;
                    acc[d+1] += pv * v4.y;
                    acc[d+2] += pv * v4.z;
                    acc[d+3] += pv * v4.w;
                }
            }
        }
    }

    const float inv = 1.f / lrun;
    float* orow = g_attn + (bh * SS + s) * 64 + half * 32;
#pragma unroll
    for (int d = 0; d < 32; d += 4) {
        float4 o4 = make_float4(acc[d]*inv, acc[d+1]*inv, acc[d+2]*inv, acc[d+3]*inv);
        *(float4*)(orow + d) = o4;
    }
}

// ---------------- global attention (rows g < G), split-K partials ----------------
__global__ __launch_bounds__(256, 1)
void gattn_part_kernel(const int* __restrict__ mask)
{
    const int split = blockIdx.x, h = blockIdx.y, b = blockIdx.z;
    const int g    = threadIdx.x & 63;
    const int part = threadIdx.x >> 6;
    const size_t bh = (size_t)b * HH + h;

    const float* qrow = g_qg + (bh * GG + g) * 64;
    float qr[64];
#pragma unroll
    for (int d = 0; d < 64; d += 4) {
        float4 t4 = *(const float4*)(qrow + d);
        qr[d] = t4.x; qr[d+1] = t4.y; qr[d+2] = t4.z; qr[d+3] = t4.w;
    }

    float acc[64];
#pragma unroll
    for (int d = 0; d < 64; d++) acc[d] = 0.f;
    float m = -1e30f, l = 0.f;

    const int p0 = split * 256 + part * 64;
    const float* kbase = g_kg + bh * SS * 64;
    const float* vbase = g_vg + bh * SS * 64;
    const int* mrow = mask + (size_t)b * SS;

    for (int kk = 0; kk < 64; kk++) {
        const int p = p0 + kk;
        const float* kr = kbase + (size_t)p * 64;
        float ssum = 0.f;
#pragma unroll
        for (int d = 0; d < 64; d += 4) {
            float4 k4 = *(const float4*)(kr + d);
            ssum += qr[d] * k4.x + qr[d+1] * k4.y + qr[d+2] * k4.z + qr[d+3] * k4.w;
        }
        if (mrow[p] > 0) ssum = -1e30f;
        float mnew = fmaxf(m, ssum);
        float corr = __expf(m - mnew);
        float pp   = __expf(ssum - mnew);
        l = l * corr + pp;
        const float* vr = vbase + (size_t)p * 64;
#pragma unroll
        for (int d = 0; d < 64; d += 4) {
            float4 v4 = *(const float4*)(vr + d);
            acc[d]   = acc[d]   * corr + pp * v4.x;
            acc[d+1] = acc[d+1] * corr + pp * v4.y;
            acc[d+2] = acc[d+2] * corr + pp * v4.z;
            acc[d+3] = acc[d+3] * corr + pp * v4.w;
        }
        m = mnew;
    }

    const size_t idx = (bh * GG + g) * 64 + (split * 4 + part);
    g_pm[idx] = m;
    g_pl[idx] = l;
    float* ap = g_pacc + idx * 64;
#pragma unroll
    for (int d = 0; d < 64; d += 4)
        *(float4*)(ap + d) = make_float4(acc[d], acc[d+1], acc[d+2], acc[d+3]);
}

__global__ void gattn_combine_kernel(void)
{
    const int rid = blockIdx.x * blockDim.x + threadIdx.x;
    if (rid >= BB * HH * GG) return;
    float M = -1e30f;
    for (int p = 0; p < 64; p++) M = fmaxf(M, g_pm[(size_t)rid * 64 + p]);
    float L = 0.f;
    float acc[64];
#pragma unroll
    for (int d = 0; d < 64; d++) acc[d] = 0.f;
    for (int p = 0; p < 64; p++) {
        const float w = __expf(g_pm[(size_t)rid * 64 + p] - M);
        L += g_pl[(size_t)rid * 64 + p] * w;
        const float* ap = g_pacc + ((size_t)rid * 64 + p) * 64;
#pragma unroll
        for (int d = 0; d < 64; d += 4) {
            float4 a4 = *(const float4*)(ap + d);
            acc[d]   += w * a4.x;
            acc[d+1] += w * a4.y;
            acc[d+2] += w * a4.z;
            acc[d+3] += w * a4.w;
        }
    }
    const float inv = 1.f / L;
    const int bh = rid >> 6, g = rid & 63;
    float* orow = g_attn + ((size_t)bh * SS + g) * 64;
#pragma unroll
    for (int d = 0; d < 64; d += 4)
        *(float4*)(orow + d) = make_float4(acc[d]*inv, acc[d+1]*inv, acc[d+2]*inv, acc[d+3]*inv);
}

// ---------------- launcher ----------------
extern "C" void kernel_launch(void* const* d_in, const int* in_sizes, int n_in,
                              void* d_out, int out_size)
{
    (void)in_sizes; (void)n_in; (void)out_size;
    const float* query = (const float*)d_in[0];
    const int*   mask  = (const int*)d_in[1];
    const float* Wq  = (const float*)d_in[2];
    const float* bq  = (const float*)d_in[3];
    const float* Wk  = (const float*)d_in[4];
    const float* bk  = (const float*)d_in[5];
    const float* Wv  = (const float*)d_in[6];
    const float* bv  = (const float*)d_in[7];
    const float* Wqg = (const float*)d_in[8];
    const float* bqg = (const float*)d_in[9];
    const float* Wkg = (const float*)d_in[10];
    const float* bkg = (const float*)d_in[11];
    const float* Wvg = (const float*)d_in[12];
    const float* bvg = (const float*)d_in[13];
    const float* Wo  = (const float*)d_in[14];
    const float* bo  = (const float*)d_in[15];
    float* out = (float*)d_out;

    float *xbuf, *qb, *kb, *vb, *kgb, *vgb, *qgb, *xat, *wt;
    cudaGetSymbolAddress((void**)&xbuf, g_xbuf);
    cudaGetSymbolAddress((void**)&qb,   g_q);
    cudaGetSymbolAddress((void**)&kb,   g_k);
    cudaGetSymbolAddress((void**)&vb,   g_v);
    cudaGetSymbolAddress((void**)&kgb,  g_kg);
    cudaGetSymbolAddress((void**)&vgb,  g_vg);
    cudaGetSymbolAddress((void**)&qgb,  g_qg);
    cudaGetSymbolAddress((void**)&xat,  g_xattn);
    cudaGetSymbolAddress((void**)&wt,   g_wt);

    cudaFuncSetAttribute(mma_gemm, cudaFuncAttributeMaxDynamicSharedMemorySize, SM_TOTAL);

    const size_t WSZ = (size_t)DD * DD;
    dim3 wtg(24, 24), wtb(32, 8);
    k_wt<<<wtg, wtb>>>(Wq,  wt + 0 * WSZ);
    k_wt<<<wtg, wtb>>>(Wk,  wt + 1 * WSZ);
    k_wt<<<wtg, wtb>>>(Wv,  wt + 2 * WSZ);
    k_wt<<<wtg, wtb>>>(Wkg, wt + 3 * WSZ);
    k_wt<<<wtg, wtb>>>(Wvg, wt + 4 * WSZ);
    k_wt<<<wtg, wtb>>>(Wqg, wt + 5 * WSZ);
    k_wt<<<wtg, wtb>>>(Wo,  wt + 6 * WSZ);

    const int ntot = BB * SS * DD;
    k_xin<<<(ntot + 255) / 256, 256>>>(query);

    dim3 gemmgrid(6, 64);   // N tiles x M tiles
    mma_gemm<<<gemmgrid, 256, SM_TOTAL>>>(xbuf, wt + 0 * WSZ, bq,  qb,  0, 0, 0.125f);
    mma_gemm<<<gemmgrid, 256, SM_TOTAL>>>(xbuf, wt + 1 * WSZ, bk,  kb,  0, 0, 1.0f);
    mma_gemm<<<gemmgrid, 256, SM_TOTAL>>>(xbuf, wt + 2 * WSZ, bv,  vb,  0, 0, 1.0f);
    mma_gemm<<<gemmgrid, 256, SM_TOTAL>>>(xbuf, wt + 3 * WSZ, bkg, kgb, 0, 0, 1.0f);
    mma_gemm<<<gemmgrid, 256, SM_TOTAL>>>(xbuf, wt + 4 * WSZ, bvg, vgb, 0, 0, 1.0f);
    mma_gemm<<<dim3(6, 1), 256, SM_TOTAL>>>(xbuf, wt + 5 * WSZ, bqg, qgb, 1, 2, 0.125f);

    local_attn_kernel<<<dim3(NCC * 2, HH, BB), 256>>>(mask);
    gattn_part_kernel<<<dim3(16, HH, BB), 256>>>(mask);
    gattn_combine_kernel<<<(BB * HH * GG + 255) / 256, 256>>>();

    k_xattn<<<(ntot + 255) / 256, 256>>>();
    mma_gemm<<<gemmgrid, 256, SM_TOTAL>>>(xat, wt + 6 * WSZ, bo, out, 0, 1, 1.0f);
}

// round 4
// speedup vs baseline: 1.9954x; 1.0478x over previous
#include <cuda_runtime.h>
#include <math.h>
#include <cstdint>

// Problem constants
#define BB 2
#define SS 4096
#define DD 768
#define HH 12
#define GG 64
#define HD 64
#define WW 256
#define NCC 16
#define NHEADS_S ((size_t)BB * HH * SS * HD)   // 6291456

// ---------------- scratch (static device globals; no allocation) ----------------
__device__ float g_xbuf [(size_t)BB * SS * DD];     // x row-major (B,S,D), tf32-rounded
__device__ float g_wt   [7][(size_t)DD * DD];       // W^T per weight, tf32-rounded
__device__ float g_q    [NHEADS_S];                 // [b][h][s][hd], scaled
__device__ float g_k    [NHEADS_S];
__device__ float g_v    [NHEADS_S];
__device__ float g_kg   [NHEADS_S];
__device__ float g_vg   [NHEADS_S];
__device__ float g_qg   [(size_t)BB * HH * GG * HD];
__device__ float g_attn [NHEADS_S];                 // attention out, head layout
__device__ float g_xattn[(size_t)BB * SS * DD];     // attention out, row-major, tf32-rounded
__device__ float g_pm   [(size_t)BB * HH * GG * 64];
__device__ float g_pl   [(size_t)BB * HH * GG * 64];
__device__ float g_pacc [(size_t)BB * HH * GG * 64 * HD];

// ---------------- helpers ----------------
__device__ __forceinline__ uint32_t smem_u32(const void* p) {
    uint32_t a;
    asm("{ .reg .u64 t; cvta.to.shared.u64 t, %1; cvt.u32.u64 %0, t; }" : "=r"(a) : "l"(p));
    return a;
}
__device__ __forceinline__ float to_tf32(float v) {
    float r;
    asm("cvt.rn.tf32.f32 %0, %1;" : "=f"(r) : "f"(v));
    return r;
}
#define CP_ASYNC16(saddr, gptr) \
    asm volatile("cp.async.cg.shared.global [%0], [%1], 16;" :: "r"(saddr), "l"(gptr))
#define CP_COMMIT() asm volatile("cp.async.commit_group;" ::: "memory")
#define CP_WAIT(N)  asm volatile("cp.async.wait_group %0;" :: "n"(N) : "memory")

// m16n8k8 tf32 mma (sm_80+ portable; runs on sm_103 tensor pipe)
#define MMA_TF32(d, a, b) \
    asm volatile( \
        "mma.sync.aligned.m16n8k8.row.col.f32.tf32.tf32.f32 " \
        "{%0,%1,%2,%3}, {%4,%5,%6,%7}, {%8,%9}, {%0,%1,%2,%3};" \
        : "+f"((d)[0]), "+f"((d)[1]), "+f"((d)[2]), "+f"((d)[3]) \
        : "r"((a)[0]), "r"((a)[1]), "r"((a)[2]), "r"((a)[3]), \
          "r"((b)[0]), "r"((b)[1]))

// ---------------- transpose: query (S,B,D) -> xbuf (B,S,D), tf32-rounded ----------------
__global__ void k_xin(const float* __restrict__ query) {
    size_t t = (size_t)blockIdx.x * blockDim.x + threadIdx.x;
    if (t >= (size_t)BB * SS * DD) return;
    int d  = (int)(t % DD);
    size_t rs = t / DD;
    int b = (int)(rs >> 12);
    int s = (int)(rs & 4095);
    g_xbuf[t] = to_tf32(query[((size_t)s * BB + b) * DD + d]);
}

// ---------------- transpose: attn head layout -> row-major (B,S,D), tf32-rounded ----------------
__global__ void k_xattn(void) {
    size_t t = (size_t)blockIdx.x * blockDim.x + threadIdx.x;
    if (t >= (size_t)BB * SS * DD) return;
    int d  = (int)(t % DD);
    size_t rs = t / DD;
    int b = (int)(rs >> 12);
    int s = (int)(rs & 4095);
    int h = d >> 6, hd = d & 63;
    g_xattn[t] = to_tf32(g_attn[(((size_t)b * HH + h) * SS + s) * 64 + hd]);
}

// ---------------- weight transposes (all 7 in one launch): WT[n][k] = rn_tf32(W[k][n]) ----------------
struct W7 { const float* w[7]; };
__global__ void k_wt_all(W7 p) {
    __shared__ float tile[32][33];
    const float* W = p.w[blockIdx.z];
    float* WT = g_wt[blockIdx.z];
    int x = blockIdx.x * 32 + threadIdx.x;   // n
    int y0 = blockIdx.y * 32;                // k base
#pragma unroll
    for (int j = 0; j < 32; j += 8)
        tile[threadIdx.y + j][threadIdx.x] = W[(size_t)(y0 + threadIdx.y + j) * DD + x];
    __syncthreads();
    int kx = y0 + threadIdx.x;               // k
#pragma unroll
    for (int j = 0; j < 32; j += 8) {
        int n = blockIdx.x * 32 + threadIdx.y + j;
        WT[(size_t)n * DD + kx] = to_tf32(tile[threadIdx.x][threadIdx.y + j]);
    }
}

// ---------------- tf32 mma.sync GEMM core ----------------
// CTA tile 128x128, 256 threads = 8 warps as 2(m) x 4(n), warp tile 64x32.
// K=768 in 24 chunks of 32, cp.async double-buffered; smem stride 36 floats.
#define ASTRIDE 36
#define OPBYTES (128 * ASTRIDE * 4)            // 18432
#define STAGEBYTES (2 * OPBYTES)               // 36864
#define SM_TOTAL (2 * STAGEBYTES)              // 73728

__device__ __forceinline__ void gemm_core(
    const float* __restrict__ X, const float* __restrict__ WT,
    const float* __restrict__ bias, float* __restrict__ Out,
    int in_mode, int out_mode, float scale, char* smem,
    int m0, int n0)
{
    const uint32_t sbase = smem_u32(smem);
    const int tid = threadIdx.x;
    const int wid = tid >> 5, lane = tid & 31;
    const int wm = (wid >> 2) * 64;
    const int wn = (wid & 3) * 32;
    const int lr = lane >> 2;
    const int lc = lane & 3;

    const float* arow[4];
    const float* brow[4];
    uint32_t dsto[4];
#pragma unroll
    for (int i = 0; i < 4; i++) {
        int li = i * 256 + tid;
        int row = li >> 3, col4 = li & 7;
        int gr = m0 + row;
        int grow = (in_mode == 0) ? gr : ((gr >> 6) * 4096 + (gr & 63));
        arow[i] = X  + (size_t)grow * 768 + col4 * 4;
        brow[i] = WT + (size_t)(n0 + row) * 768 + col4 * 4;
        dsto[i] = (uint32_t)(row * (ASTRIDE * 4) + col4 * 16);
    }

    float acc[4][4][4];
#pragma unroll
    for (int mt = 0; mt < 4; mt++)
#pragma unroll
        for (int nt = 0; nt < 4; nt++)
#pragma unroll
            for (int e = 0; e < 4; e++) acc[mt][nt][e] = 0.f;

    {
        uint32_t sa = sbase, sb = sbase + OPBYTES;
#pragma unroll
        for (int i = 0; i < 4; i++) {
            CP_ASYNC16(sa + dsto[i], arow[i]);
            CP_ASYNC16(sb + dsto[i], brow[i]);
        }
        CP_COMMIT();
    }

    for (int c = 0; c < 24; c++) {
        if (c < 23) {
            const int k0n = (c + 1) * 32;
            const uint32_t st = ((c + 1) & 1) * STAGEBYTES;
            uint32_t sa = sbase + st, sb = sbase + st + OPBYTES;
#pragma unroll
            for (int i = 0; i < 4; i++) {
                CP_ASYNC16(sa + dsto[i], arow[i] + k0n);
                CP_ASYNC16(sb + dsto[i], brow[i] + k0n);
            }
            CP_COMMIT();
            CP_WAIT(1);
        } else {
            CP_WAIT(0);
        }
        __syncthreads();

        const uint32_t st = (c & 1) * STAGEBYTES;
        const uint32_t* As = (const uint32_t*)(smem + st);
        const uint32_t* Bs = (const uint32_t*)(smem + st + OPBYTES);

#pragma unroll
        for (int ks = 0; ks < 4; ks++) {
            const int k0 = ks * 8;
            uint32_t af[4][4];
#pragma unroll
            for (int mt = 0; mt < 4; mt++) {
                int r0 = wm + mt * 16 + lr;
                af[mt][0] = As[(r0)     * ASTRIDE + k0 + lc];
                af[mt][1] = As[(r0 + 8) * ASTRIDE + k0 + lc];
                af[mt][2] = As[(r0)     * ASTRIDE + k0 + 4 + lc];
                af[mt][3] = As[(r0 + 8) * ASTRIDE + k0 + 4 + lc];
            }
            uint32_t bf[4][2];
#pragma unroll
            for (int nt = 0; nt < 4; nt++) {
                int nrow = wn + nt * 8 + lr;
                bf[nt][0] = Bs[nrow * ASTRIDE + k0 + lc];
                bf[nt][1] = Bs[nrow * ASTRIDE + k0 + 4 + lc];
            }
#pragma unroll
            for (int mt = 0; mt < 4; mt++)
#pragma unroll
                for (int nt = 0; nt < 4; nt++)
                    MMA_TF32(acc[mt][nt], af[mt], bf[nt]);
        }
        __syncthreads();
    }

#pragma unroll
    for (int mt = 0; mt < 4; mt++) {
#pragma unroll
        for (int half = 0; half < 2; half++) {
            const int rr = m0 + wm + mt * 16 + lr + half * 8;
#pragma unroll
            for (int nt = 0; nt < 4; nt++) {
                const int nn = n0 + wn + nt * 8 + lc * 2;
                float v0 = (acc[mt][nt][half * 2 + 0] + bias[nn])     * scale;
                float v1 = (acc[mt][nt][half * 2 + 1] + bias[nn + 1]) * scale;
                float* ptr;
                if (out_mode == 0) {
                    int bb = rr >> 12, ss = rr & 4095;
                    int h = nn >> 6, hd0 = nn & 63;
                    ptr = Out + ((((size_t)bb * HH + h) * SS + ss) * 64 + hd0);
                } else if (out_mode == 1) {
                    int bb = rr >> 12, ss = rr & 4095;
                    ptr = Out + ((size_t)ss * BB + bb) * DD + nn;
                } else {
                    int bb = rr >> 6, gg2 = rr & 63;
                    int h = nn >> 6, hd0 = nn & 63;
                    ptr = Out + ((((size_t)bb * HH + h) * GG + gg2) * 64 + hd0);
                }
                *(float2*)ptr = make_float2(v0, v1);
            }
        }
    }
}

// batched: 5 full GEMMs (q, k, v, kg, vg) in one launch, z selects the problem
struct Gemm5 { const float* bias[5]; float* out[5]; float scale[5]; };
__global__ __launch_bounds__(256, 2)
void mma_gemm5(const float* __restrict__ X, Gemm5 p)
{
    extern __shared__ char smem[];
    const int z = blockIdx.z;
    gemm_core(X, g_wt[z], p.bias[z], p.out[z], 0, 0, p.scale[z], smem,
              blockIdx.y * 128, blockIdx.x * 128);
}

__global__ __launch_bounds__(256, 2)
void mma_gemm(const float* __restrict__ X, const float* __restrict__ WT,
              const float* __restrict__ bias, float* __restrict__ Out,
              int in_mode, int out_mode, float scale)
{
    extern __shared__ char smem[];
    gemm_core(X, WT, bias, Out, in_mode, out_mode, scale, smem,
              blockIdx.y * 128, blockIdx.x * 128);
}

// ---------------- local windowed attention (+ global columns) ----------------
// grid (NC*2, H, B), 256 threads: 128 q rows per CTA, 2 threads per row (HD split).
// Score groups of 16 to keep register state at qr[32]+acc[32]+sc[16]=80 floats (no spills).
__global__ __launch_bounds__(256, 2)
void local_attn_kernel(const int* __restrict__ mask)
{
    const int c = blockIdx.x >> 1, h = blockIdx.y, b = blockIdx.z;
    const int rhalf = blockIdx.x & 1;
    const int i = rhalf * 128 + (threadIdx.x >> 1);   // row within chunk 0..255
    const int half = threadIdx.x & 1;
    const int s = c * WW + i;
    const size_t bh = (size_t)b * HH + h;

    const float* qrow = g_q + (bh * SS + s) * 64 + half * 32;
    float qr[32];
#pragma unroll
    for (int d = 0; d < 32; d += 4) {
        float4 t4 = *(const float4*)(qrow + d);
        qr[d] = t4.x; qr[d+1] = t4.y; qr[d+2] = t4.z; qr[d+3] = t4.w;
    }

    float acc[32];
#pragma unroll
    for (int d = 0; d < 32; d++) acc[d] = 0.f;
    float mrun = -1e30f, lrun = 0.f;

    __shared__ float ks[64][68];
    __shared__ float vs[64][68];
    __shared__ int   okf[64];

    const float* kbase = g_k + bh * SS * 64;
    const float* vbase = g_v + bh * SS * 64;
    const int r0 = rhalf * 128;              // row range [r0, r0+127]

    for (int t = 0; t < 13; t++) {
        if (t >= 1) {
            const int jlo = (t - 1) * 64;
            if (jlo + 63 < r0 || jlo > r0 + 127 + 2 * WW) continue;
        }
        const int pbase = (t == 0) ? 0 : (c - 1) * WW + (t - 1) * 64;

        __syncthreads();
        {
            int row  = threadIdx.x >> 2;           // 0..63
            int col0 = (threadIdx.x & 3) * 16;
            int p = pbase + row;
            bool inr = (p >= 0 && p < SS);
            const float* kr = kbase + (size_t)(inr ? p : 0) * 64;
            const float* vr = vbase + (size_t)(inr ? p : 0) * 64;
#pragma unroll
            for (int e = 0; e < 16; e += 4) {
                float4 kv = inr ? *(const float4*)(kr + col0 + e) : make_float4(0,0,0,0);
                float4 vv = inr ? *(const float4*)(vr + col0 + e) : make_float4(0,0,0,0);
                *(float4*)&ks[row][col0 + e] = kv;
                *(float4*)&vs[row][col0 + e] = vv;
            }
            if ((threadIdx.x & 3) == 0) {
                bool okp;
                if (t == 0) okp = true;
                else        okp = inr && (mask[b * SS + p] == 0);
                okf[row] = okp ? 1 : 0;
            }
        }
        __syncthreads();

        const int jtile0 = (t - 1) * 64;
#pragma unroll
        for (int qg4 = 0; qg4 < 4; qg4++) {        // 4 groups of 16 cols
            float sc[16];
            float mc = -1e30f;
#pragma unroll
            for (int jj = 0; jj < 16; jj++) {
                const int j2 = qg4 * 16 + jj;
                float ssum = 0.f;
#pragma unroll
                for (int d = 0; d < 32; d += 4) {
                    float4 k4 = *(const float4*)&ks[j2][half * 32 + d];
                    ssum += qr[d] * k4.x + qr[d+1] * k4.y + qr[d+2] * k4.z + qr[d+3] * k4.w;
                }
                ssum += __shfl_xor_sync(0xffffffffu, ssum, 1);
                bool ok;
                if (t == 0) ok = true;
                else {
                    int j = jtile0 + j2;
                    ok = (j >= i) && (j <= i + 2 * WW) && (okf[j2] != 0);
                }
                sc[jj] = ok ? ssum : -1e30f;
                mc = fmaxf(mc, sc[jj]);
            }
            float mnew = fmaxf(mrun, mc);
            float corr = __expf(mrun - mnew);
            lrun *= corr;
#pragma unroll
            for (int d = 0; d < 32; d++) acc[d] *= corr;
            float psum = 0.f;
#pragma unroll
            for (int jj = 0; jj < 16; jj++) {
                float pp = __expf(sc[jj] - mnew);
                sc[jj] = pp;
                psum += pp;
            }
            lrun += psum;
            mrun = mnew;
#pragma unroll
            for (int jj = 0; jj < 16; jj++) {
                const int j2 = qg4 * 16 + jj;
                const float pv = sc[jj];
#pragma unroll
                for (int d = 0; d < 32; d += 4) {
                    float4 v4 = *(const float4*)&vs[j2][half * 32 + d];
                    acc[d]   += pv * v4.x;
                    acc[d+1] += pv * v4.y;
                    acc[d+2] += pv * v4.z;
                    acc[d+3] += pv * v4.w;
                }
            }
        }
    }

    const float inv = 1.f / lrun;
    float* orow = g_attn + (bh * SS + s) * 64 + half * 32;
#pragma unroll
    for (int d = 0; d < 32; d += 4) {
        float4 o4 = make_float4(acc[d]*inv, acc[d+1]*inv, acc[d+2]*inv, acc[d+3]*inv);
        *(float4*)(orow + d) = o4;
    }
}

// ---------------- global attention (rows g < G), split-K partials ----------------
// chunk-8 scores before each acc rescale (cuts softmax bookkeeping ~3x)
__global__ __launch_bounds__(256, 1)
void gattn_part_kernel(const int* __restrict__ mask)
{
    const int split = blockIdx.x, h = blockIdx.y, b = blockIdx.z;
    const int g    = threadIdx.x & 63;
    const int part = threadIdx.x >> 6;
    const size_t bh = (size_t)b * HH + h;

    const float* qrow = g_qg + (bh * GG + g) * 64;
    float qr[64];
#pragma unroll
    for (int d = 0; d < 64; d += 4) {
        float4 t4 = *(const float4*)(qrow + d);
        qr[d] = t4.x; qr[d+1] = t4.y; qr[d+2] = t4.z; qr[d+3] = t4.w;
    }

    float acc[64];
#pragma unroll
    for (int d = 0; d < 64; d++) acc[d] = 0.f;
    float m = -1e30f, l = 0.f;

    const int p0 = split * 256 + part * 64;
    const float* kbase = g_kg + bh * SS * 64;
    const float* vbase = g_vg + bh * SS * 64;
    const int* mrow = mask + (size_t)b * SS;

    for (int ch = 0; ch < 8; ch++) {
        float sc[8];
        float mc = -1e30f;
#pragma unroll
        for (int kk = 0; kk < 8; kk++) {
            const int p = p0 + ch * 8 + kk;
            const float* kr = kbase + (size_t)p * 64;
            float ssum = 0.f;
#pragma unroll
            for (int d = 0; d < 64; d += 4) {
                float4 k4 = *(const float4*)(kr + d);
                ssum += qr[d] * k4.x + qr[d+1] * k4.y + qr[d+2] * k4.z + qr[d+3] * k4.w;
            }
            if (mrow[p] > 0) ssum = -1e30f;
            sc[kk] = ssum;
            mc = fmaxf(mc, ssum);
        }
        float mnew = fmaxf(m, mc);
        float corr = __expf(m - mnew);
        l *= corr;
#pragma unroll
        for (int d = 0; d < 64; d++) acc[d] *= corr;
#pragma unroll
        for (int kk = 0; kk < 8; kk++) {
            float pp = __expf(sc[kk] - mnew);
            l += pp;
            const float* vr = vbase + (size_t)(p0 + ch * 8 + kk) * 64;
#pragma unroll
            for (int d = 0; d < 64; d += 4) {
                float4 v4 = *(const float4*)(vr + d);
                acc[d]   += pp * v4.x;
                acc[d+1] += pp * v4.y;
                acc[d+2] += pp * v4.z;
                acc[d+3] += pp * v4.w;
            }
        }
        m = mnew;
    }

    const size_t idx = (bh * GG + g) * 64 + (split * 4 + part);
    g_pm[idx] = m;
    g_pl[idx] = l;
    float* ap = g_pacc + idx * 64;
#pragma unroll
    for (int d = 0; d < 64; d += 4)
        *(float4*)(ap + d) = make_float4(acc[d], acc[d+1], acc[d+2], acc[d+3]);
}

__global__ void gattn_combine_kernel(void)
{
    const int rid = blockIdx.x * blockDim.x + threadIdx.x;
    if (rid >= BB * HH * GG) return;
    float M = -1e30f;
    for (int p = 0; p < 64; p++) M = fmaxf(M, g_pm[(size_t)rid * 64 + p]);
    float L = 0.f;
    float acc[64];
#pragma unroll
    for (int d = 0; d < 64; d++) acc[d] = 0.f;
    for (int p = 0; p < 64; p++) {
        const float w = __expf(g_pm[(size_t)rid * 64 + p] - M);
        L += g_pl[(size_t)rid * 64 + p] * w;
        const float* ap = g_pacc + ((size_t)rid * 64 + p) * 64;
#pragma unroll
        for (int d = 0; d < 64; d += 4) {
            float4 a4 = *(const float4*)(ap + d);
            acc[d]   += w * a4.x;
            acc[d+1] += w * a4.y;
            acc[d+2] += w * a4.z;
            acc[d+3] += w * a4.w;
        }
    }
    const float inv = 1.f / L;
    const int bh = rid >> 6, g = rid & 63;
    float* orow = g_attn + ((size_t)bh * SS + g) * 64;
#pragma unroll
    for (int d = 0; d < 64; d += 4)
        *(float4*)(orow + d) = make_float4(acc[d]*inv, acc[d+1]*inv, acc[d+2]*inv, acc[d+3]*inv);
}

// ---------------- launcher ----------------
extern "C" void kernel_launch(void* const* d_in, const int* in_sizes, int n_in,
                              void* d_out, int out_size)
{
    (void)in_sizes; (void)n_in; (void)out_size;
    const float* query = (const float*)d_in[0];
    const int*   mask  = (const int*)d_in[1];
    const float* Wq  = (const float*)d_in[2];
    const float* bq  = (const float*)d_in[3];
    const float* Wk  = (const float*)d_in[4];
    const float* bk  = (const float*)d_in[5];
    const float* Wv  = (const float*)d_in[6];
    const float* bv  = (const float*)d_in[7];
    const float* Wqg = (const float*)d_in[8];
    const float* bqg = (const float*)d_in[9];
    const float* Wkg = (const float*)d_in[10];
    const float* bkg = (const float*)d_in[11];
    const float* Wvg = (const float*)d_in[12];
    const float* bvg = (const float*)d_in[13];
    const float* Wo  = (const float*)d_in[14];
    const float* bo  = (const float*)d_in[15];
    float* out = (float*)d_out;

    float *xbuf, *qb, *kb, *vb, *kgb, *vgb, *qgb, *xat, *wt;
    cudaGetSymbolAddress((void**)&xbuf, g_xbuf);
    cudaGetSymbolAddress((void**)&qb,   g_q);
    cudaGetSymbolAddress((void**)&kb,   g_k);
    cudaGetSymbolAddress((void**)&vb,   g_v);
    cudaGetSymbolAddress((void**)&kgb,  g_kg);
    cudaGetSymbolAddress((void**)&vgb,  g_vg);
    cudaGetSymbolAddress((void**)&qgb,  g_qg);
    cudaGetSymbolAddress((void**)&xat,  g_xattn);
    cudaGetSymbolAddress((void**)&wt,   g_wt);

    cudaFuncSetAttribute(mma_gemm,  cudaFuncAttributeMaxDynamicSharedMemorySize, SM_TOTAL);
    cudaFuncSetAttribute(mma_gemm5, cudaFuncAttributeMaxDynamicSharedMemorySize, SM_TOTAL);

    const size_t WSZ = (size_t)DD * DD;

    // launch 0: all weight transposes  (wt order: 0=q 1=k 2=v 3=kg 4=vg 5=qg 6=o)
    W7 w7;
    w7.w[0] = Wq; w7.w[1] = Wk; w7.w[2] = Wv; w7.w[3] = Wkg;
    w7.w[4] = Wvg; w7.w[5] = Wqg; w7.w[6] = Wo;
    k_wt_all<<<dim3(24, 24, 7), dim3(32, 8)>>>(w7);

    // launch 1: input transpose
    const int ntot = BB * SS * DD;
    k_xin<<<(ntot + 255) / 256, 256>>>(query);

    // launch 2: 5 batched head GEMMs (q, k, v, kg, vg)
    Gemm5 p5;
    p5.bias[0] = bq;  p5.out[0] = qb;  p5.scale[0] = 0.125f;
    p5.bias[1] = bk;  p5.out[1] = kb;  p5.scale[1] = 1.0f;
    p5.bias[2] = bv;  p5.out[2] = vb;  p5.scale[2] = 1.0f;
    p5.bias[3] = bkg; p5.out[3] = kgb; p5.scale[3] = 1.0f;
    p5.bias[4] = bvg; p5.out[4] = vgb; p5.scale[4] = 1.0f;
    mma_gemm5<<<dim3(6, 64, 5), 256, SM_TOTAL>>>(xbuf, p5);

    // launch 3: qg GEMM (gathered 128 rows)
    mma_gemm<<<dim3(6, 1), 256, SM_TOTAL>>>(xbuf, wt + 5 * WSZ, bqg, qgb, 1, 2, 0.125f);

    // launch 4: global attention partials
    gattn_part_kernel<<<dim3(16, HH, BB), 256>>>(mask);

    // launch 5: local attention  (this is the launch ncu -s 5 -c 1 profiles)
    local_attn_kernel<<<dim3(NCC * 2, HH, BB), 256>>>(mask);

    // launch 6..8
    gattn_combine_kernel<<<(BB * HH * GG + 255) / 256, 256>>>();
    k_xattn<<<(ntot + 255) / 256, 256>>>();
    mma_gemm<<<dim3(6, 64), 256, SM_TOTAL>>>(xat, wt + 6 * WSZ, bo, out, 0, 1, 1.0f);
}

// round 5
// speedup vs baseline: 3.9807x; 1.9949x over previous
#include <cuda_runtime.h>
#include <math.h>
#include <cstdint>

// Problem constants
#define BB 2
#define SS 4096
#define DD 768
#define HH 12
#define GG 64
#define HD 64
#define WW 256
#define NCC 16
#define NHEADS_S ((size_t)BB * HH * SS * HD)   // 6291456

// ---------------- scratch (static device globals; no allocation) ----------------
__device__ float g_xbuf [(size_t)BB * SS * DD];
__device__ float g_wt   [7][(size_t)DD * DD];
__device__ float g_q    [NHEADS_S];
__device__ float g_k    [NHEADS_S];
__device__ float g_v    [NHEADS_S];
__device__ float g_kg   [NHEADS_S];
__device__ float g_vg   [NHEADS_S];
__device__ float g_qg   [(size_t)BB * HH * GG * HD];
__device__ float g_attn [NHEADS_S];
__device__ float g_xattn[(size_t)BB * SS * DD];
__device__ float g_pm   [(size_t)BB * HH * GG * 64];
__device__ float g_pl   [(size_t)BB * HH * GG * 64];
__device__ float g_pacc [(size_t)BB * HH * GG * 64 * HD];

// ---------------- helpers ----------------
__device__ __forceinline__ uint32_t smem_u32(const void* p) {
    uint32_t a;
    asm("{ .reg .u64 t; cvta.to.shared.u64 t, %1; cvt.u32.u64 %0, t; }" : "=r"(a) : "l"(p));
    return a;
}
__device__ __forceinline__ float to_tf32(float v) {
    float r;
    asm("cvt.rn.tf32.f32 %0, %1;" : "=f"(r) : "f"(v));
    return r;
}
// fast exp on the FMA pipe: e^x = 2^(x*log2e), degree-6 poly for 2^f, f in [0,1)
__device__ __forceinline__ float fexp(float x) {
    float t = fmaxf(x * 1.4426950408889634f, -126.0f);
    float fi = floorf(t);
    float f = t - fi;
    float p = 1.5418e-4f;
    p = fmaf(p, f, 1.3333558146e-3f);
    p = fmaf(p, f, 9.6181291108e-3f);
    p = fmaf(p, f, 5.5504108664e-2f);
    p = fmaf(p, f, 2.4022650696e-1f);
    p = fmaf(p, f, 6.9314718056e-1f);
    p = fmaf(p, f, 1.0f);
    return __int_as_float(((int)fi + 127) << 23) * p;
}
#define CP_ASYNC16(saddr, gptr) \
    asm volatile("cp.async.cg.shared.global [%0], [%1], 16;" :: "r"(saddr), "l"(gptr))
#define CP_COMMIT() asm volatile("cp.async.commit_group;" ::: "memory")
#define CP_WAIT(N)  asm volatile("cp.async.wait_group %0;" :: "n"(N) : "memory")

// m16n8k8 tf32 mma (sm_80+ portable; runs on sm_103 tensor pipe)
#define MMA_TF32(d, a, b) \
    asm volatile( \
        "mma.sync.aligned.m16n8k8.row.col.f32.tf32.tf32.f32 " \
        "{%0,%1,%2,%3}, {%4,%5,%6,%7}, {%8,%9}, {%0,%1,%2,%3};" \
        : "+f"((d)[0]), "+f"((d)[1]), "+f"((d)[2]), "+f"((d)[3]) \
        : "r"((a)[0]), "r"((a)[1]), "r"((a)[2]), "r"((a)[3]), \
          "r"((b)[0]), "r"((b)[1]))

// ---------------- transposes ----------------
__global__ void k_xin(const float* __restrict__ query) {
    size_t t = (size_t)blockIdx.x * blockDim.x + threadIdx.x;
    if (t >= (size_t)BB * SS * DD) return;
    int d  = (int)(t % DD);
    size_t rs = t / DD;
    int b = (int)(rs >> 12);
    int s = (int)(rs & 4095);
    g_xbuf[t] = to_tf32(query[((size_t)s * BB + b) * DD + d]);
}
__global__ void k_xattn(void) {
    size_t t = (size_t)blockIdx.x * blockDim.x + threadIdx.x;
    if (t >= (size_t)BB * SS * DD) return;
    int d  = (int)(t % DD);
    size_t rs = t / DD;
    int b = (int)(rs >> 12);
    int s = (int)(rs & 4095);
    int h = d >> 6, hd = d & 63;
    g_xattn[t] = to_tf32(g_attn[(((size_t)b * HH + h) * SS + s) * 64 + hd]);
}
struct W7 { const float* w[7]; };
__global__ void k_wt_all(W7 p) {
    __shared__ float tile[32][33];
    const float* W = p.w[blockIdx.z];
    float* WT = g_wt[blockIdx.z];
    int x = blockIdx.x * 32 + threadIdx.x;
    int y0 = blockIdx.y * 32;
#pragma unroll
    for (int j = 0; j < 32; j += 8)
        tile[threadIdx.y + j][threadIdx.x] = W[(size_t)(y0 + threadIdx.y + j) * DD + x];
    __syncthreads();
    int kx = y0 + threadIdx.x;
#pragma unroll
    for (int j = 0; j < 32; j += 8) {
        int n = blockIdx.x * 32 + threadIdx.y + j;
        WT[(size_t)n * DD + kx] = to_tf32(tile[threadIdx.x][threadIdx.y + j]);
    }
}

// ---------------- tf32 mma.sync GEMM core ----------------
#define ASTRIDE 36
#define OPBYTES (128 * ASTRIDE * 4)
#define STAGEBYTES (2 * OPBYTES)
#define SM_TOTAL (2 * STAGEBYTES)

__device__ __forceinline__ void gemm_core(
    const float* __restrict__ X, const float* __restrict__ WT,
    const float* __restrict__ bias, float* __restrict__ Out,
    int in_mode, int out_mode, float scale, char* smem,
    int m0, int n0)
{
    const uint32_t sbase = smem_u32(smem);
    const int tid = threadIdx.x;
    const int wid = tid >> 5, lane = tid & 31;
    const int wm = (wid >> 2) * 64;
    const int wn = (wid & 3) * 32;
    const int lr = lane >> 2;
    const int lc = lane & 3;

    const float* arow[4];
    const float* brow[4];
    uint32_t dsto[4];
#pragma unroll
    for (int i = 0; i < 4; i++) {
        int li = i * 256 + tid;
        int row = li >> 3, col4 = li & 7;
        int gr = m0 + row;
        int grow = (in_mode == 0) ? gr : ((gr >> 6) * 4096 + (gr & 63));
        arow[i] = X  + (size_t)grow * 768 + col4 * 4;
        brow[i] = WT + (size_t)(n0 + row) * 768 + col4 * 4;
        dsto[i] = (uint32_t)(row * (ASTRIDE * 4) + col4 * 16);
    }

    float acc[4][4][4];
#pragma unroll
    for (int mt = 0; mt < 4; mt++)
#pragma unroll
        for (int nt = 0; nt < 4; nt++)
#pragma unroll
            for (int e = 0; e < 4; e++) acc[mt][nt][e] = 0.f;

    {
        uint32_t sa = sbase, sb = sbase + OPBYTES;
#pragma unroll
        for (int i = 0; i < 4; i++) {
            CP_ASYNC16(sa + dsto[i], arow[i]);
            CP_ASYNC16(sb + dsto[i], brow[i]);
        }
        CP_COMMIT();
    }

    for (int c = 0; c < 24; c++) {
        if (c < 23) {
            const int k0n = (c + 1) * 32;
            const uint32_t st = ((c + 1) & 1) * STAGEBYTES;
            uint32_t sa = sbase + st, sb = sbase + st + OPBYTES;
#pragma unroll
            for (int i = 0; i < 4; i++) {
                CP_ASYNC16(sa + dsto[i], arow[i] + k0n);
                CP_ASYNC16(sb + dsto[i], brow[i] + k0n);
            }
            CP_COMMIT();
            CP_WAIT(1);
        } else {
            CP_WAIT(0);
        }
        __syncthreads();

        const uint32_t st = (c & 1) * STAGEBYTES;
        const uint32_t* As = (const uint32_t*)(smem + st);
        const uint32_t* Bs = (const uint32_t*)(smem + st + OPBYTES);

#pragma unroll
        for (int ks = 0; ks < 4; ks++) {
            const int k0 = ks * 8;
            uint32_t af[4][4];
#pragma unroll
            for (int mt = 0; mt < 4; mt++) {
                int r0 = wm + mt * 16 + lr;
                af[mt][0] = As[(r0)     * ASTRIDE + k0 + lc];
                af[mt][1] = As[(r0 + 8) * ASTRIDE + k0 + lc];
                af[mt][2] = As[(r0)     * ASTRIDE + k0 + 4 + lc];
                af[mt][3] = As[(r0 + 8) * ASTRIDE + k0 + 4 + lc];
            }
            uint32_t bf[4][2];
#pragma unroll
            for (int nt = 0; nt < 4; nt++) {
                int nrow = wn + nt * 8 + lr;
                bf[nt][0] = Bs[nrow * ASTRIDE + k0 + lc];
                bf[nt][1] = Bs[nrow * ASTRIDE + k0 + 4 + lc];
            }
#pragma unroll
            for (int mt = 0; mt < 4; mt++)
#pragma unroll
                for (int nt = 0; nt < 4; nt++)
                    MMA_TF32(acc[mt][nt], af[mt], bf[nt]);
        }
        __syncthreads();
    }

#pragma unroll
    for (int mt = 0; mt < 4; mt++) {
#pragma unroll
        for (int half = 0; half < 2; half++) {
            const int rr = m0 + wm + mt * 16 + lr + half * 8;
#pragma unroll
            for (int nt = 0; nt < 4; nt++) {
                const int nn = n0 + wn + nt * 8 + lc * 2;
                float v0 = (acc[mt][nt][half * 2 + 0] + bias[nn])     * scale;
                float v1 = (acc[mt][nt][half * 2 + 1] + bias[nn + 1]) * scale;
                float* ptr;
                if (out_mode == 0) {
                    int bb = rr >> 12, ss = rr & 4095;
                    int h = nn >> 6, hd0 = nn & 63;
                    ptr = Out + ((((size_t)bb * HH + h) * SS + ss) * 64 + hd0);
                } else if (out_mode == 1) {
                    int bb = rr >> 12, ss = rr & 4095;
                    ptr = Out + ((size_t)ss * BB + bb) * DD + nn;
                } else {
                    int bb = rr >> 6, gg2 = rr & 63;
                    int h = nn >> 6, hd0 = nn & 63;
                    ptr = Out + ((((size_t)bb * HH + h) * GG + gg2) * 64 + hd0);
                }
                *(float2*)ptr = make_float2(v0, v1);
            }
        }
    }
}

// batched: 6 GEMMs (q,k,v,kg,vg full; qg = z 5, m-tile 0 only)
struct Gemm6 { const float* bias[6]; float* out[6]; float scale[6]; };
__global__ __launch_bounds__(256, 2)
void mma_gemm6(const float* __restrict__ X, Gemm6 p)
{
    extern __shared__ char smem[];
    const int z = blockIdx.z;
    if (z == 5) {
        if (blockIdx.y != 0) return;
        gemm_core(X, g_wt[5], p.bias[5], p.out[5], 1, 2, p.scale[5], smem,
                  0, blockIdx.x * 128);
    } else {
        gemm_core(X, g_wt[z], p.bias[z], p.out[z], 0, 0, p.scale[z], smem,
                  blockIdx.y * 128, blockIdx.x * 128);
    }
}
__global__ __launch_bounds__(256, 2)
void mma_gemm(const float* __restrict__ X, const float* __restrict__ WT,
              const float* __restrict__ bias, float* __restrict__ Out,
              int in_mode, int out_mode, float scale)
{
    extern __shared__ char smem[];
    gemm_core(X, WT, bias, Out, in_mode, out_mode, scale, smem,
              blockIdx.y * 128, blockIdx.x * 128);
}

// ---------------- tensor-core local windowed attention ----------------
// grid (NC*2, H, B), 256 threads = 8 warps. CTA = 128 q rows (half chunk) x band.
// Warp w: rows [w*16, w*16+16). 11 key tiles of 64 (1 global + 10 band).
// S = Q K^T via m16n8k8 tf32; fragment online softmax (fexp on FMA pipe);
// P routed through per-warp smem; O += P V via m16n8k8 tf32.
#define KS_STR 68
#define VS_STR 72
#define PS_STR 68
#define LA_KS_OFF 0
#define LA_VS_OFF (64 * KS_STR * 4)                       // 17408
#define LA_PS_OFF (LA_VS_OFF + 64 * VS_STR * 4)           // 35840
#define LA_PS_WARP (16 * PS_STR * 4)                      // 4352
#define LA_OKF_OFF (LA_PS_OFF + 8 * LA_PS_WARP)           // 70656
#define LA_SMEM (LA_OKF_OFF + 64 * 4)                     // 70912

__global__ __launch_bounds__(256, 2)
void local_attn_tc(const int* __restrict__ mask)
{
    extern __shared__ char sm[];
    float* ks  = (float*)(sm + LA_KS_OFF);
    float* vs  = (float*)(sm + LA_VS_OFF);
    int*   okf = (int*)  (sm + LA_OKF_OFF);

    const int c = blockIdx.x >> 1, h = blockIdx.y, b = blockIdx.z;
    const int rhalf = blockIdx.x & 1;
    const int i0 = rhalf * 128;
    const int tid = threadIdx.x, wid = tid >> 5, lane = tid & 31;
    const int lr = lane >> 2, lc = lane & 3;
    const size_t bh = (size_t)b * HH + h;
    const int s0 = c * WW + i0;
    float* ps = (float*)(sm + LA_PS_OFF + wid * LA_PS_WARP);

    // Q fragments (rows w*16+lr, +8; cols kstep*8+lc, +4), pre-rounded to tf32
    uint32_t qa[8][4];
    {
        const float* qb2 = g_q + (bh * SS + s0 + wid * 16) * 64;
#pragma unroll
        for (int kk = 0; kk < 8; kk++) {
            qa[kk][0] = __float_as_uint(to_tf32(qb2[(lr)     * 64 + kk * 8 + lc]));
            qa[kk][1] = __float_as_uint(to_tf32(qb2[(lr + 8) * 64 + kk * 8 + lc]));
            qa[kk][2] = __float_as_uint(to_tf32(qb2[(lr)     * 64 + kk * 8 + lc + 4]));
            qa[kk][3] = __float_as_uint(to_tf32(qb2[(lr + 8) * 64 + kk * 8 + lc + 4]));
        }
    }

    float o[8][4];
#pragma unroll
    for (int nt = 0; nt < 8; nt++)
#pragma unroll
        for (int e = 0; e < 4; e++) o[nt][e] = 0.f;
    float m[2] = { -1e30f, -1e30f };
    float l[2] = { 0.f, 0.f };

    const float* kbase = g_k + bh * SS * 64;
    const float* vbase = g_v + bh * SS * 64;
    const int tlo = rhalf ? 2 : 0;
    const int iA = i0 + wid * 16 + lr;     // within-chunk row of frag row 0
    const int iB = iA + 8;

    for (int ti = 0; ti < 11; ti++) {
        const bool isg = (ti == 0);
        const int tt = tlo + ti - 1;                      // band tile idx (ti>=1)
        const int pbase = isg ? 0 : (c - 1) * WW + tt * 64;
        if (!isg && (pbase >= SS || pbase + 63 < 0)) continue;

        __syncthreads();
        {
            int row = tid >> 2, c0 = (tid & 3) * 16;
            int p = pbase + row;
            bool inr = (p >= 0 && p < SS);
            const float* kr = kbase + (size_t)(inr ? p : 0) * 64;
            const float* vr = vbase + (size_t)(inr ? p : 0) * 64;
#pragma unroll
            for (int e = 0; e < 16; e += 4) {
                float4 kv = inr ? *(const float4*)(kr + c0 + e) : make_float4(0,0,0,0);
                float4 vv = inr ? *(const float4*)(vr + c0 + e) : make_float4(0,0,0,0);
                kv.x = to_tf32(kv.x); kv.y = to_tf32(kv.y);
                kv.z = to_tf32(kv.z); kv.w = to_tf32(kv.w);
                vv.x = to_tf32(vv.x); vv.y = to_tf32(vv.y);
                vv.z = to_tf32(vv.z); vv.w = to_tf32(vv.w);
                *(float4*)&ks[row * KS_STR + c0 + e] = kv;
                *(float4*)&vs[row * VS_STR + c0 + e] = vv;
            }
            if ((tid & 3) == 0)
                okf[row] = isg ? 1 : ((inr && (mask[b * SS + p] == 0)) ? 1 : 0);
        }
        __syncthreads();

        // ---- S = Q @ K^T (warp tile 16 x 64) ----
        float cs[8][4];
#pragma unroll
        for (int nt = 0; nt < 8; nt++)
#pragma unroll
            for (int e = 0; e < 4; e++) cs[nt][e] = 0.f;
#pragma unroll
        for (int kk = 0; kk < 8; kk++) {
            const int k0 = kk * 8;
#pragma unroll
            for (int nt = 0; nt < 8; nt++) {
                uint32_t bf[2];
                bf[0] = __float_as_uint(ks[(nt * 8 + lr) * KS_STR + k0 + lc]);
                bf[1] = __float_as_uint(ks[(nt * 8 + lr) * KS_STR + k0 + lc + 4]);
                MMA_TF32(cs[nt], qa[kk], bf);
            }
        }

        // ---- masking ----
        if (!isg) {
#pragma unroll
            for (int nt = 0; nt < 8; nt++) {
                const int jl = nt * 8 + 2 * lc;
                const int j  = tt * 64 + jl;
                const bool k0ok = okf[jl] != 0;
                const bool k1ok = okf[jl + 1] != 0;
                if (!(k0ok && j     >= iA && j     <= iA + 2*WW)) cs[nt][0] = -1e30f;
                if (!(k1ok && j + 1 >= iA && j + 1 <= iA + 2*WW)) cs[nt][1] = -1e30f;
                if (!(k0ok && j     >= iB && j     <= iB + 2*WW)) cs[nt][2] = -1e30f;
                if (!(k1ok && j + 1 >= iB && j + 1 <= iB + 2*WW)) cs[nt][3] = -1e30f;
            }
        }

        // ---- fragment online softmax (per row e: lr / lr+8) ----
#pragma unroll
        for (int e = 0; e < 2; e++) {
            float mloc = -1e30f;
#pragma unroll
            for (int nt = 0; nt < 8; nt++)
                mloc = fmaxf(mloc, fmaxf(cs[nt][2*e], cs[nt][2*e + 1]));
            mloc = fmaxf(mloc, __shfl_xor_sync(0xffffffffu, mloc, 1));
            mloc = fmaxf(mloc, __shfl_xor_sync(0xffffffffu, mloc, 2));
            float mnew = fmaxf(m[e], mloc);
            float corr = fexp(m[e] - mnew);
            m[e] = mnew;
            float psum = 0.f;
            const int prow = lr + 8 * e;
#pragma unroll
            for (int nt = 0; nt < 8; nt++) {
                float p0 = fexp(cs[nt][2*e]     - mnew);
                float p1 = fexp(cs[nt][2*e + 1] - mnew);
                psum += p0 + p1;
                *(float2*)&ps[prow * PS_STR + nt * 8 + 2 * lc] =
                    make_float2(to_tf32(p0), to_tf32(p1));
                o[nt][2*e]     *= corr;
                o[nt][2*e + 1] *= corr;
            }
            l[e] = l[e] * corr + psum;
        }
        __syncwarp();

        // ---- O += P @ V ----
#pragma unroll
        for (int kk = 0; kk < 8; kk++) {
            const int k0 = kk * 8;
            uint32_t af[4];
            af[0] = __float_as_uint(ps[(lr)     * PS_STR + k0 + lc]);
            af[1] = __float_as_uint(ps[(lr + 8) * PS_STR + k0 + lc]);
            af[2] = __float_as_uint(ps[(lr)     * PS_STR + k0 + lc + 4]);
            af[3] = __float_as_uint(ps[(lr + 8) * PS_STR + k0 + lc + 4]);
#pragma unroll
            for (int nt = 0; nt < 8; nt++) {
                uint32_t bf[2];
                bf[0] = __float_as_uint(vs[(k0 + lc)     * VS_STR + nt * 8 + lr]);
                bf[1] = __float_as_uint(vs[(k0 + lc + 4) * VS_STR + nt * 8 + lr]);
                MMA_TF32(o[nt], af, bf);
            }
        }
        __syncwarp();
    }

    // ---- normalize + write ----
#pragma unroll
    for (int e = 0; e < 2; e++) {
        float ll = l[e];
        ll += __shfl_xor_sync(0xffffffffu, ll, 1);
        ll += __shfl_xor_sync(0xffffffffu, ll, 2);
        const float inv = 1.f / ll;
        const int srow = s0 + wid * 16 + lr + 8 * e;
        float* orow = g_attn + (bh * SS + srow) * 64;
#pragma unroll
        for (int nt = 0; nt < 8; nt++)
            *(float2*)&orow[nt * 8 + 2 * lc] =
                make_float2(o[nt][2*e] * inv, o[nt][2*e + 1] * inv);
    }
}

// ---------------- global attention (rows g < G), split-K partials ----------------
__global__ __launch_bounds__(256, 1)
void gattn_part_kernel(const int* __restrict__ mask)
{
    const int split = blockIdx.x, h = blockIdx.y, b = blockIdx.z;
    const int g    = threadIdx.x & 63;
    const int part = threadIdx.x >> 6;
    const size_t bh = (size_t)b * HH + h;

    const float* qrow = g_qg + (bh * GG + g) * 64;
    float qr[64];
#pragma unroll
    for (int d = 0; d < 64; d += 4) {
        float4 t4 = *(const float4*)(qrow + d);
        qr[d] = t4.x; qr[d+1] = t4.y; qr[d+2] = t4.z; qr[d+3] = t4.w;
    }

    float acc[64];
#pragma unroll
    for (int d = 0; d < 64; d++) acc[d] = 0.f;
    float m = -1e30f, l = 0.f;

    const int p0 = split * 256 + part * 64;
    const float* kbase = g_kg + bh * SS * 64;
    const float* vbase = g_vg + bh * SS * 64;
    const int* mrow = mask + (size_t)b * SS;

    for (int ch = 0; ch < 8; ch++) {
        float sc[8];
        float mc = -1e30f;
#pragma unroll
        for (int kk = 0; kk < 8; kk++) {
            const int p = p0 + ch * 8 + kk;
            const float* kr = kbase + (size_t)p * 64;
            float ssum = 0.f;
#pragma unroll
            for (int d = 0; d < 64; d += 4) {
                float4 k4 = *(const float4*)(kr + d);
                ssum += qr[d] * k4.x + qr[d+1] * k4.y + qr[d+2] * k4.z + qr[d+3] * k4.w;
            }
            if (mrow[p] > 0) ssum = -1e30f;
            sc[kk] = ssum;
            mc = fmaxf(mc, ssum);
        }
        float mnew = fmaxf(m, mc);
        float corr = fexp(m - mnew);
        l *= corr;
#pragma unroll
        for (int d = 0; d < 64; d++) acc[d] *= corr;
#pragma unroll
        for (int kk = 0; kk < 8; kk++) {
            float pp = fexp(sc[kk] - mnew);
            l += pp;
            const float* vr = vbase + (size_t)(p0 + ch * 8 + kk) * 64;
#pragma unroll
            for (int d = 0; d < 64; d += 4) {
                float4 v4 = *(const float4*)(vr + d);
                acc[d]   += pp * v4.x;
                acc[d+1] += pp * v4.y;
                acc[d+2] += pp * v4.z;
                acc[d+3] += pp * v4.w;
            }
        }
        m = mnew;
    }

    const size_t idx = (bh * GG + g) * 64 + (split * 4 + part);
    g_pm[idx] = m;
    g_pl[idx] = l;
    float* ap = g_pacc + idx * 64;
#pragma unroll
    for (int d = 0; d < 64; d += 4)
        *(float4*)(ap + d) = make_float4(acc[d], acc[d+1], acc[d+2], acc[d+3]);
}

__global__ void gattn_combine_kernel(void)
{
    const int rid = blockIdx.x * blockDim.x + threadIdx.x;
    if (rid >= BB * HH * GG) return;
    float M = -1e30f;
    for (int p = 0; p < 64; p++) M = fmaxf(M, g_pm[(size_t)rid * 64 + p]);
    float L = 0.f;
    float acc[64];
#pragma unroll
    for (int d = 0; d < 64; d++) acc[d] = 0.f;
    for (int p = 0; p < 64; p++) {
        const float w = fexp(g_pm[(size_t)rid * 64 + p] - M);
        L += g_pl[(size_t)rid * 64 + p] * w;
        const float* ap = g_pacc + ((size_t)rid * 64 + p) * 64;
#pragma unroll
        for (int d = 0; d < 64; d += 4) {
            float4 a4 = *(const float4*)(ap + d);
            acc[d]   += w * a4.x;
            acc[d+1] += w * a4.y;
            acc[d+2] += w * a4.z;
            acc[d+3] += w * a4.w;
        }
    }
    const float inv = 1.f / L;
    const int bh = rid >> 6, g = rid & 63;
    float* orow = g_attn + ((size_t)bh * SS + g) * 64;
#pragma unroll
    for (int d = 0; d < 64; d += 4)
        *(float4*)(orow + d) = make_float4(acc[d]*inv, acc[d+1]*inv, acc[d+2]*inv, acc[d+3]*inv);
}

// ---------------- launcher ----------------
extern "C" void kernel_launch(void* const* d_in, const int* in_sizes, int n_in,
                              void* d_out, int out_size)
{
    (void)in_sizes; (void)n_in; (void)out_size;
    const float* query = (const float*)d_in[0];
    const int*   mask  = (const int*)d_in[1];
    const float* Wq  = (const float*)d_in[2];
    const float* bq  = (const float*)d_in[3];
    const float* Wk  = (const float*)d_in[4];
    const float* bk  = (const float*)d_in[5];
    const float* Wv  = (const float*)d_in[6];
    const float* bv  = (const float*)d_in[7];
    const float* Wqg = (const float*)d_in[8];
    const float* bqg = (const float*)d_in[9];
    const float* Wkg = (const float*)d_in[10];
    const float* bkg = (const float*)d_in[11];
    const float* Wvg = (const float*)d_in[12];
    const float* bvg = (const float*)d_in[13];
    const float* Wo  = (const float*)d_in[14];
    const float* bo  = (const float*)d_in[15];
    float* out = (float*)d_out;

    float *xbuf, *qb, *kb, *vb, *kgb, *vgb, *qgb, *xat, *wt;
    cudaGetSymbolAddress((void**)&xbuf, g_xbuf);
    cudaGetSymbolAddress((void**)&qb,   g_q);
    cudaGetSymbolAddress((void**)&kb,   g_k);
    cudaGetSymbolAddress((void**)&vb,   g_v);
    cudaGetSymbolAddress((void**)&kgb,  g_kg);
    cudaGetSymbolAddress((void**)&vgb,  g_vg);
    cudaGetSymbolAddress((void**)&qgb,  g_qg);
    cudaGetSymbolAddress((void**)&xat,  g_xattn);
    cudaGetSymbolAddress((void**)&wt,   g_wt);

    cudaFuncSetAttribute(mma_gemm,      cudaFuncAttributeMaxDynamicSharedMemorySize, SM_TOTAL);
    cudaFuncSetAttribute(mma_gemm6,     cudaFuncAttributeMaxDynamicSharedMemorySize, SM_TOTAL);
    cudaFuncSetAttribute(local_attn_tc, cudaFuncAttributeMaxDynamicSharedMemorySize, LA_SMEM);

    const size_t WSZ = (size_t)DD * DD;

    // launch 0: weight transposes (wt: 0=q 1=k 2=v 3=kg 4=vg 5=qg 6=o)
    W7 w7;
    w7.w[0] = Wq; w7.w[1] = Wk; w7.w[2] = Wv; w7.w[3] = Wkg;
    w7.w[4] = Wvg; w7.w[5] = Wqg; w7.w[6] = Wo;
    k_wt_all<<<dim3(24, 24, 7), dim3(32, 8)>>>(w7);

    // launch 1: input transpose
    const int ntot = BB * SS * DD;
    k_xin<<<(ntot + 255) / 256, 256>>>(query);

    // launch 2: 6 batched GEMMs (q, k, v, kg, vg, qg)
    Gemm6 p6;
    p6.bias[0] = bq;  p6.out[0] = qb;  p6.scale[0] = 0.125f;
    p6.bias[1] = bk;  p6.out[1] = kb;  p6.scale[1] = 1.0f;
    p6.bias[2] = bv;  p6.out[2] = vb;  p6.scale[2] = 1.0f;
    p6.bias[3] = bkg; p6.out[3] = kgb; p6.scale[3] = 1.0f;
    p6.bias[4] = bvg; p6.out[4] = vgb; p6.scale[4] = 1.0f;
    p6.bias[5] = bqg; p6.out[5] = qgb; p6.scale[5] = 0.125f;
    mma_gemm6<<<dim3(6, 64, 6), 256, SM_TOTAL>>>(xbuf, p6);

    // launch 3: tensor-core local attention (profile slot)
    local_attn_tc<<<dim3(NCC * 2, HH, BB), 256, LA_SMEM>>>(mask);

    // launch 4,5: global attention
    gattn_part_kernel<<<dim3(16, HH, BB), 256>>>(mask);
    gattn_combine_kernel<<<(BB * HH * GG + 255) / 256, 256>>>();

    // launch 6,7: output transpose + final GEMM
    k_xattn<<<(ntot + 255) / 256, 256>>>();
    mma_gemm<<<dim3(6, 64), 256, SM_TOTAL>>>(xat, wt + 6 * WSZ, bo, out, 0, 1, 1.0f);
}

// round 6
// speedup vs baseline: 6.6282x; 1.6651x over previous
#include <cuda_runtime.h>
#include <cuda_fp16.h>
#include <math.h>
#include <cstdint>

// Problem constants
#define BB 2
#define SS 4096
#define DD 768
#define HH 12
#define GG 64
#define HD 64
#define WW 256
#define NCC 16
#define NHEADS_S ((size_t)BB * HH * SS * HD)   // 6291456

// ---------------- scratch (static device globals; no allocation) ----------------
__device__ __half g_xh  [(size_t)BB * SS * DD];      // x (B,S,D) fp16
__device__ __half g_wth [7][(size_t)DD * DD];        // W^T fp16
__device__ __half g_qh  [NHEADS_S];                  // [b][h][s][hd] scaled
__device__ __half g_kh  [NHEADS_S];
__device__ __half g_vh  [NHEADS_S];
__device__ __half g_kgh [NHEADS_S];
__device__ __half g_vgh [NHEADS_S];
__device__ __half g_qgh [(size_t)BB * HH * GG * HD];
__device__ __half g_attnh[NHEADS_S];                 // attention out, head layout
__device__ __half g_xatth[(size_t)BB * SS * DD];     // attention out, row-major
__device__ float g_pm   [(size_t)BB * HH * GG * 64];
__device__ float g_pl   [(size_t)BB * HH * GG * 64];
__device__ float g_pacc [(size_t)BB * HH * GG * 64 * HD];

// ---------------- helpers ----------------
__device__ __forceinline__ uint32_t smem_u32(const void* p) {
    uint32_t a;
    asm("{ .reg .u64 t; cvta.to.shared.u64 t, %1; cvt.u32.u64 %0, t; }" : "=r"(a) : "l"(p));
    return a;
}
__device__ __forceinline__ uint32_t packh2(float a, float b) {
    __half2 h = __floats2half2_rn(a, b);
    return *reinterpret_cast<uint32_t*>(&h);
}
// fast exp on the FMA pipe
__device__ __forceinline__ float fexp(float x) {
    float t = fmaxf(x * 1.4426950408889634f, -126.0f);
    float fi = floorf(t);
    float f = t - fi;
    float p = 1.5418e-4f;
    p = fmaf(p, f, 1.3333558146e-3f);
    p = fmaf(p, f, 9.6181291108e-3f);
    p = fmaf(p, f, 5.5504108664e-2f);
    p = fmaf(p, f, 2.4022650696e-1f);
    p = fmaf(p, f, 6.9314718056e-1f);
    p = fmaf(p, f, 1.0f);
    return __int_as_float(((int)fi + 127) << 23) * p;
}
#define CP_ASYNC16(saddr, gptr) \
    asm volatile("cp.async.cg.shared.global [%0], [%1], 16;" :: "r"(saddr), "l"(gptr))
#define CP_COMMIT() asm volatile("cp.async.commit_group;" ::: "memory")
#define CP_WAIT(N)  asm volatile("cp.async.wait_group %0;" :: "n"(N) : "memory")

// fp16 m16n8k16 mma, fp32 accumulate
#define MMA_F16(d, a, b0v, b1v) \
    asm volatile( \
        "mma.sync.aligned.m16n8k16.row.col.f32.f16.f16.f32 " \
        "{%0,%1,%2,%3}, {%4,%5,%6,%7}, {%8,%9}, {%0,%1,%2,%3};" \
        : "+f"((d)[0]), "+f"((d)[1]), "+f"((d)[2]), "+f"((d)[3]) \
        : "r"((a)[0]), "r"((a)[1]), "r"((a)[2]), "r"((a)[3]), \
          "r"(b0v), "r"(b1v))

#define LDSM_X4(r0, r1, r2, r3, addr) \
    asm volatile("ldmatrix.sync.aligned.m8n8.x4.shared.b16 {%0,%1,%2,%3}, [%4];" \
                 : "=r"(r0), "=r"(r1), "=r"(r2), "=r"(r3) : "r"(addr))
#define LDSM_X4_T(r0, r1, r2, r3, addr) \
    asm volatile("ldmatrix.sync.aligned.m8n8.x4.trans.shared.b16 {%0,%1,%2,%3}, [%4];" \
                 : "=r"(r0), "=r"(r1), "=r"(r2), "=r"(r3) : "r"(addr))

// ---------------- transposes ----------------
__global__ void k_xin(const float* __restrict__ query) {
    size_t t = (size_t)blockIdx.x * blockDim.x + threadIdx.x;
    if (t >= (size_t)BB * SS * DD) return;
    int d  = (int)(t % DD);
    size_t rs = t / DD;
    int b = (int)(rs >> 12);
    int s = (int)(rs & 4095);
    g_xh[t] = __float2half_rn(query[((size_t)s * BB + b) * DD + d]);
}
__global__ void k_xattn(void) {
    size_t t = (size_t)blockIdx.x * blockDim.x + threadIdx.x;   // half2 pairs
    if (t >= (size_t)BB * SS * DD / 2) return;
    int d2 = (int)(t % 384);
    size_t rs = t / 384;
    int b = (int)(rs >> 12);
    int s = (int)(rs & 4095);
    int d = d2 * 2;
    int h = d >> 6, hd = d & 63;
    *(uint32_t*)&g_xatth[rs * DD + d] =
        *(const uint32_t*)&g_attnh[(((size_t)b * HH + h) * SS + s) * 64 + hd];
}
struct W7 { const float* w[7]; };
__global__ void k_wt_all(W7 p) {
    __shared__ float tile[32][33];
    const float* W = p.w[blockIdx.z];
    __half* WT = g_wth[blockIdx.z];
    int x = blockIdx.x * 32 + threadIdx.x;
    int y0 = blockIdx.y * 32;
#pragma unroll
    for (int j = 0; j < 32; j += 8)
        tile[threadIdx.y + j][threadIdx.x] = W[(size_t)(y0 + threadIdx.y + j) * DD + x];
    __syncthreads();
    int kx = y0 + threadIdx.x;
#pragma unroll
    for (int j = 0; j < 32; j += 8) {
        int n = blockIdx.x * 32 + threadIdx.y + j;
        WT[(size_t)n * DD + kx] = __float2half_rn(tile[threadIdx.x][threadIdx.y + j]);
    }
}

// ---------------- fp16 mma.sync GEMM core ----------------
// CTA 128x128, 256 thr = 8 warps 2(m)x4(n), warp tile 64x32. K=768 in 24 chunks
// of 32 halves, double-buffered cp.async. Row stride 20 u32 (conflict-free frags).
#define AH 20
#define OPB (128 * AH * 4)        // 10240
#define STG (2 * OPB)             // 20480
#define SMT (2 * STG)             // 40960

__device__ __forceinline__ void gemm_core_h(
    const __half* __restrict__ X, const __half* __restrict__ WT,
    const float* __restrict__ bias, float* __restrict__ OutF, __half* __restrict__ OutH,
    int in_mode, int out_mode, float scale, char* smem, int m0, int n0)
{
    const uint32_t sbase = smem_u32(smem);
    const int tid = threadIdx.x;
    const int wid = tid >> 5, lane = tid & 31;
    const int wm = (wid >> 2) * 64;
    const int wn = (wid & 3) * 32;
    const int lr = lane >> 2;
    const int lc = lane & 3;

    const __half* arow[2];
    const __half* brow[2];
    uint32_t dsto[2];
#pragma unroll
    for (int i = 0; i < 2; i++) {
        int li = i * 256 + tid;
        int row = li >> 2, col4 = li & 3;
        int gr = m0 + row;
        int grow = (in_mode == 0) ? gr : ((gr >> 6) * 4096 + (gr & 63));
        arow[i] = X  + (size_t)grow * 768 + col4 * 8;
        brow[i] = WT + (size_t)(n0 + row) * 768 + col4 * 8;
        dsto[i] = (uint32_t)(row * 80 + col4 * 16);
    }

    float acc[4][4][4];
#pragma unroll
    for (int mt = 0; mt < 4; mt++)
#pragma unroll
        for (int nt = 0; nt < 4; nt++)
#pragma unroll
            for (int e = 0; e < 4; e++) acc[mt][nt][e] = 0.f;

    {
        uint32_t sa = sbase, sb = sbase + OPB;
#pragma unroll
        for (int i = 0; i < 2; i++) {
            CP_ASYNC16(sa + dsto[i], arow[i]);
            CP_ASYNC16(sb + dsto[i], brow[i]);
        }
        CP_COMMIT();
    }

    for (int c = 0; c < 24; c++) {
        if (c < 23) {
            const int kn = (c + 1) * 32;
            const uint32_t st = ((c + 1) & 1) * STG;
            uint32_t sa = sbase + st, sb = sbase + st + OPB;
#pragma unroll
            for (int i = 0; i < 2; i++) {
                CP_ASYNC16(sa + dsto[i], arow[i] + kn);
                CP_ASYNC16(sb + dsto[i], brow[i] + kn);
            }
            CP_COMMIT();
            CP_WAIT(1);
        } else {
            CP_WAIT(0);
        }
        __syncthreads();

        const uint32_t st = (c & 1) * STG;
        const uint32_t* As = (const uint32_t*)(smem + st);
        const uint32_t* Bs = (const uint32_t*)(smem + st + OPB);

#pragma unroll
        for (int ks = 0; ks < 2; ks++) {
            const int k0 = ks * 8;
            uint32_t af[4][4];
#pragma unroll
            for (int mt = 0; mt < 4; mt++) {
                int r0 = wm + mt * 16 + lr;
                af[mt][0] = As[(r0)     * AH + k0 + lc];
                af[mt][1] = As[(r0 + 8) * AH + k0 + lc];
                af[mt][2] = As[(r0)     * AH + k0 + 4 + lc];
                af[mt][3] = As[(r0 + 8) * AH + k0 + 4 + lc];
            }
            uint32_t bf[4][2];
#pragma unroll
            for (int nt = 0; nt < 4; nt++) {
                int nrow = wn + nt * 8 + lr;
                bf[nt][0] = Bs[nrow * AH + k0 + lc];
                bf[nt][1] = Bs[nrow * AH + k0 + 4 + lc];
            }
#pragma unroll
            for (int mt = 0; mt < 4; mt++)
#pragma unroll
                for (int nt = 0; nt < 4; nt++)
                    MMA_F16(acc[mt][nt], af[mt], bf[nt][0], bf[nt][1]);
        }
        __syncthreads();
    }

#pragma unroll
    for (int mt = 0; mt < 4; mt++) {
#pragma unroll
        for (int half = 0; half < 2; half++) {
            const int rr = m0 + wm + mt * 16 + lr + half * 8;
#pragma unroll
            for (int nt = 0; nt < 4; nt++) {
                const int nn = n0 + wn + nt * 8 + lc * 2;
                float v0 = (acc[mt][nt][half * 2 + 0] + bias[nn])     * scale;
                float v1 = (acc[mt][nt][half * 2 + 1] + bias[nn + 1]) * scale;
                if (out_mode == 1) {
                    int bb = rr >> 12, ss = rr & 4095;
                    *(float2*)(OutF + ((size_t)ss * BB + bb) * DD + nn) = make_float2(v0, v1);
                } else if (out_mode == 0) {
                    int bb = rr >> 12, ss = rr & 4095;
                    int h = nn >> 6, hd0 = nn & 63;
                    *(uint32_t*)(OutH + ((((size_t)bb * HH + h) * SS + ss) * 64 + hd0)) = packh2(v0, v1);
                } else {
                    int bb = rr >> 6, gg2 = rr & 63;
                    int h = nn >> 6, hd0 = nn & 63;
                    *(uint32_t*)(OutH + ((((size_t)bb * HH + h) * GG + gg2) * 64 + hd0)) = packh2(v0, v1);
                }
            }
        }
    }
}

// batched: 6 GEMMs (q,k,v,kg,vg full; qg = z 5, m-tile 0 only)
struct Gemm6 { const float* bias[6]; __half* out[6]; float scale[6]; };
__global__ __launch_bounds__(256, 2)
void mma_gemm6(Gemm6 p)
{
    __shared__ char smem[SMT];
    const int z = blockIdx.z;
    if (z == 5) {
        if (blockIdx.y != 0) return;
        gemm_core_h(g_xh, g_wth[5], p.bias[5], nullptr, p.out[5], 1, 2, p.scale[5], smem,
                    0, blockIdx.x * 128);
    } else {
        gemm_core_h(g_xh, g_wth[z], p.bias[z], nullptr, p.out[z], 0, 0, p.scale[z], smem,
                    blockIdx.y * 128, blockIdx.x * 128);
    }
}
__global__ __launch_bounds__(256, 2)
void mma_gemm_out(const float* __restrict__ bias, float* __restrict__ Out)
{
    __shared__ char smem[SMT];
    gemm_core_h(g_xatth, g_wth[6], bias, Out, nullptr, 0, 1, 1.0f, smem,
                blockIdx.y * 128, blockIdx.x * 128);
}

// ---------------- fp16 tensor-core local windowed attention ----------------
// grid (NC*2, H, B), 256 thr = 8 warps; CTA = 128 q rows; 11 tiles of 64 keys
// (1 global + 10 band), K/V half tiles (stride 72 halves), double-buffered.
// B-frags via ldmatrix (K non-trans, V trans); P stays in registers (layout match).
#define KSTR 72
__global__ __launch_bounds__(256, 2)
void local_attn_tc(const int* __restrict__ mask)
{
    __shared__ __align__(16) __half ksm[2][64 * KSTR];
    __shared__ __align__(16) __half vsm[2][64 * KSTR];
    __shared__ unsigned char okarr[704];

    const int c = blockIdx.x >> 1, h = blockIdx.y, b = blockIdx.z;
    const int rhalf = blockIdx.x & 1;
    const int i0 = rhalf * 128;
    const int tid = threadIdx.x, wid = tid >> 5, lane = tid & 31;
    const int lr = lane >> 2, lc = lane & 3;
    const int l8 = lane & 7, lb = (lane >> 3) & 1, lh = lane >> 4;
    const size_t bh = (size_t)b * HH + h;
    const int s0 = c * WW + i0;
    const int tlo = rhalf * 2;
    const int bandlo = (c - 1) * WW + tlo * 64;

    // ok flags: [0,64) global keys, [64,704) band positions
    for (int j = tid; j < 704; j += 256) {
        int ok;
        if (j < 64) ok = 1;
        else {
            int p = bandlo + (j - 64);
            ok = (p >= 0 && p < SS && mask[b * SS + p] == 0) ? 1 : 0;
        }
        okarr[j] = (unsigned char)ok;
    }

    // Q fragments from global (half)
    uint32_t qa[4][4];
    {
        const __half* qb2 = g_qh + (bh * SS + s0 + wid * 16) * 64;
#pragma unroll
        for (int kk = 0; kk < 4; kk++) {
            qa[kk][0] = *(const uint32_t*)&qb2[(lr)     * 64 + kk * 16 + 2 * lc];
            qa[kk][1] = *(const uint32_t*)&qb2[(lr + 8) * 64 + kk * 16 + 2 * lc];
            qa[kk][2] = *(const uint32_t*)&qb2[(lr)     * 64 + kk * 16 + 8 + 2 * lc];
            qa[kk][3] = *(const uint32_t*)&qb2[(lr + 8) * 64 + kk * 16 + 8 + 2 * lc];
        }
    }

    float o[8][4];
#pragma unroll
    for (int nt = 0; nt < 8; nt++)
#pragma unroll
        for (int e = 0; e < 4; e++) o[nt][e] = 0.f;
    float mrun[2] = { -1e30f, -1e30f };
    float lrun[2] = { 0.f, 0.f };

    const __half* kbase = g_kh + bh * SS * 64;
    const __half* vbase = g_vh + bh * SS * 64;
    const int irelA = i0 + wid * 16 + lr;
    const int irelB = irelA + 8;

    // tile loader: 1024 cp.async chunks (512 K + 512 V) / 256 thr = 4 each
    auto issue_tile = [&](int ti, int buf) {
        const int pbase = (ti == 0) ? 0 : bandlo + (ti - 1) * 64;
        const uint32_t kdst = smem_u32(&ksm[buf][0]);
        const uint32_t vdst = smem_u32(&vsm[buf][0]);
#pragma unroll
        for (int i = 0; i < 4; i++) {
            int li = i * 256 + tid;
            int op = li >> 9;
            int rem = li & 511;
            int row = rem >> 3, ch = rem & 7;
            int p = pbase + row;
            p = (p < 0) ? 0 : ((p >= SS) ? SS - 1 : p);
            const __half* src = (op ? vbase : kbase) + (size_t)p * 64 + ch * 8;
            uint32_t dst = (op ? vdst : kdst) + (uint32_t)(row * (KSTR * 2) + ch * 16);
            CP_ASYNC16(dst, src);
        }
        CP_COMMIT();
    };

    issue_tile(0, 0);

    for (int ti = 0; ti < 11; ti++) {
        if (ti < 10) { issue_tile(ti + 1, (ti + 1) & 1); CP_WAIT(1); }
        else         { CP_WAIT(0); }
        __syncthreads();

        const uint32_t kbuf = smem_u32(&ksm[ti & 1][0]);
        const uint32_t vbuf = smem_u32(&vsm[ti & 1][0]);

        // S = Q K^T
        float cs[8][4];
#pragma unroll
        for (int nt = 0; nt < 8; nt++)
#pragma unroll
            for (int e = 0; e < 4; e++) cs[nt][e] = 0.f;
#pragma unroll
        for (int kk = 0; kk < 4; kk++) {
#pragma unroll
            for (int g4 = 0; g4 < 4; g4++) {
                uint32_t r0, r1, r2, r3;
                int key = g4 * 16 + l8 + lb * 8;
                int dim = kk * 16 + lh * 8;
                LDSM_X4(r0, r1, r2, r3, kbuf + (uint32_t)(key * (KSTR * 2) + dim * 2));
                MMA_F16(cs[2 * g4],     qa[kk], r0, r2);
                MMA_F16(cs[2 * g4 + 1], qa[kk], r1, r3);
            }
        }

        // mask (band + key-ok); tile 0 (global keys) unmasked
        if (ti > 0) {
            const int jbase = (tlo + ti - 1) * 64;
            const unsigned char* okp = okarr + 64 + (ti - 1) * 64;
#pragma unroll
            for (int nt = 0; nt < 8; nt++) {
                int jl = nt * 8 + 2 * lc;
                int j = jbase + jl;
                bool o0 = okp[jl] != 0, o1 = okp[jl + 1] != 0;
                if (!(o0 && j     >= irelA && j     <= irelA + 512)) cs[nt][0] = -1e30f;
                if (!(o1 && j + 1 >= irelA && j + 1 <= irelA + 512)) cs[nt][1] = -1e30f;
                if (!(o0 && j     >= irelB && j     <= irelB + 512)) cs[nt][2] = -1e30f;
                if (!(o1 && j + 1 >= irelB && j + 1 <= irelB + 512)) cs[nt][3] = -1e30f;
            }
        }

        // online softmax (rows lr / lr+8); P packed directly into A-fragments
        float ml0 = -1e30f, ml1 = -1e30f;
#pragma unroll
        for (int nt = 0; nt < 8; nt++) {
            ml0 = fmaxf(ml0, fmaxf(cs[nt][0], cs[nt][1]));
            ml1 = fmaxf(ml1, fmaxf(cs[nt][2], cs[nt][3]));
        }
        ml0 = fmaxf(ml0, __shfl_xor_sync(0xffffffffu, ml0, 1));
        ml0 = fmaxf(ml0, __shfl_xor_sync(0xffffffffu, ml0, 2));
        ml1 = fmaxf(ml1, __shfl_xor_sync(0xffffffffu, ml1, 1));
        ml1 = fmaxf(ml1, __shfl_xor_sync(0xffffffffu, ml1, 2));
        float mn0 = fmaxf(mrun[0], ml0), mn1 = fmaxf(mrun[1], ml1);
        float corr0 = fexp(mrun[0] - mn0), corr1 = fexp(mrun[1] - mn1);
        mrun[0] = mn0; mrun[1] = mn1;
        float ps0 = 0.f, ps1 = 0.f;
        uint32_t pa[4][4];
#pragma unroll
        for (int nt = 0; nt < 8; nt++) {
            float p0 = fexp(cs[nt][0] - mn0);
            float p1 = fexp(cs[nt][1] - mn0);
            float p2 = fexp(cs[nt][2] - mn1);
            float p3 = fexp(cs[nt][3] - mn1);
            ps0 += p0 + p1; ps1 += p2 + p3;
            pa[nt >> 1][(nt & 1) * 2 + 0] = packh2(p0, p1);
            pa[nt >> 1][(nt & 1) * 2 + 1] = packh2(p2, p3);
            o[nt][0] *= corr0; o[nt][1] *= corr0;
            o[nt][2] *= corr1; o[nt][3] *= corr1;
        }
        lrun[0] = lrun[0] * corr0 + ps0;
        lrun[1] = lrun[1] * corr1 + ps1;

        // O += P V (V via ldmatrix.trans)
#pragma unroll
        for (int kk = 0; kk < 4; kk++) {
#pragma unroll
            for (int g4 = 0; g4 < 4; g4++) {
                uint32_t r0, r1, r2, r3;
                int key = kk * 16 + l8 + lb * 8;
                int dim = g4 * 16 + lh * 8;
                LDSM_X4_T(r0, r1, r2, r3, vbuf + (uint32_t)(key * (KSTR * 2) + dim * 2));
                MMA_F16(o[2 * g4],     pa[kk], r0, r1);
                MMA_F16(o[2 * g4 + 1], pa[kk], r2, r3);
            }
        }
        __syncthreads();
    }

    // normalize + write (half)
#pragma unroll
    for (int e = 0; e < 2; e++) {
        float ll = lrun[e];
        ll += __shfl_xor_sync(0xffffffffu, ll, 1);
        ll += __shfl_xor_sync(0xffffffffu, ll, 2);
        const float inv = 1.f / ll;
        const int srow = s0 + wid * 16 + lr + 8 * e;
        __half* orow = g_attnh + (bh * SS + srow) * 64;
#pragma unroll
        for (int nt = 0; nt < 8; nt++)
            *(uint32_t*)&orow[nt * 8 + 2 * lc] =
                packh2(o[nt][2 * e] * inv, o[nt][2 * e + 1] * inv);
    }
}

// ---------------- fp16 tensor-core global attention (split-K partials) ----------------
// grid (32, H, B), 256 thr = 8 warps: warp = (row-tile wid&3, key-half wid>>2).
// CTA covers 128 keys; each warp one 16x64 tile, single-pass softmax, partial out.
__global__ __launch_bounds__(256, 2)
void gattn_part_tc(const int* __restrict__ mask)
{
    __shared__ __align__(16) __half kgs[128 * KSTR];
    __shared__ __align__(16) __half vgs[128 * KSTR];
    __shared__ unsigned char okg[128];

    const int split = blockIdx.x, h = blockIdx.y, b = blockIdx.z;
    const int tid = threadIdx.x, wid = tid >> 5, lane = tid & 31;
    const int lr = lane >> 2, lc = lane & 3;
    const int l8 = lane & 7, lb = (lane >> 3) & 1, lh = lane >> 4;
    const size_t bh = (size_t)b * HH + h;
    const int wr = wid & 3, kh = wid >> 2;
    const int p0 = split * 128;

    // load K/V tile (2048 chunks / 256 thr = 8 each) + ok flags
    {
        const __half* kb2 = g_kgh + (bh * SS + p0) * 64;
        const __half* vb2 = g_vgh + (bh * SS + p0) * 64;
        const uint32_t kdst = smem_u32(kgs);
        const uint32_t vdst = smem_u32(vgs);
#pragma unroll
        for (int i = 0; i < 8; i++) {
            int li = i * 256 + tid;
            int op = li >> 10;
            int rem = li & 1023;
            int row = rem >> 3, ch = rem & 7;
            const __half* src = (op ? vb2 : kb2) + (size_t)row * 64 + ch * 8;
            uint32_t dst = (op ? vdst : kdst) + (uint32_t)(row * (KSTR * 2) + ch * 16);
            CP_ASYNC16(dst, src);
        }
        CP_COMMIT();
        if (tid < 128) okg[tid] = (mask[b * SS + p0 + tid] <= 0) ? 1 : 0;
        CP_WAIT(0);
        __syncthreads();
    }

    // Q fragments (rows wr*16 + lr, +8)
    uint32_t qa[4][4];
    {
        const __half* qb2 = g_qgh + (bh * GG + wr * 16) * 64;
#pragma unroll
        for (int kk = 0; kk < 4; kk++) {
            qa[kk][0] = *(const uint32_t*)&qb2[(lr)     * 64 + kk * 16 + 2 * lc];
            qa[kk][1] = *(const uint32_t*)&qb2[(lr + 8) * 64 + kk * 16 + 2 * lc];
            qa[kk][2] = *(const uint32_t*)&qb2[(lr)     * 64 + kk * 16 + 8 + 2 * lc];
            qa[kk][3] = *(const uint32_t*)&qb2[(lr + 8) * 64 + kk * 16 + 8 + 2 * lc];
        }
    }

    const uint32_t kbuf = smem_u32(kgs) + (uint32_t)(kh * 64 * KSTR * 2);
    const uint32_t vbuf = smem_u32(vgs) + (uint32_t)(kh * 64 * KSTR * 2);

    // S = Q K^T
    float cs[8][4];
#pragma unroll
    for (int nt = 0; nt < 8; nt++)
#pragma unroll
        for (int e = 0; e < 4; e++) cs[nt][e] = 0.f;
#pragma unroll
    for (int kk = 0; kk < 4; kk++) {
#pragma unroll
        for (int g4 = 0; g4 < 4; g4++) {
            uint32_t r0, r1, r2, r3;
            int key = g4 * 16 + l8 + lb * 8;
            int dim = kk * 16 + lh * 8;
            LDSM_X4(r0, r1, r2, r3, kbuf + (uint32_t)(key * (KSTR * 2) + dim * 2));
            MMA_F16(cs[2 * g4],     qa[kk], r0, r2);
            MMA_F16(cs[2 * g4 + 1], qa[kk], r1, r3);
        }
    }
    // pad mask
#pragma unroll
    for (int nt = 0; nt < 8; nt++) {
        int jl = kh * 64 + nt * 8 + 2 * lc;
        if (!okg[jl])     { cs[nt][0] = -1e30f; cs[nt][2] = -1e30f; }
        if (!okg[jl + 1]) { cs[nt][1] = -1e30f; cs[nt][3] = -1e30f; }
    }
    // single-pass softmax
    float ml0 = -1e30f, ml1 = -1e30f;
#pragma unroll
    for (int nt = 0; nt < 8; nt++) {
        ml0 = fmaxf(ml0, fmaxf(cs[nt][0], cs[nt][1]));
        ml1 = fmaxf(ml1, fmaxf(cs[nt][2], cs[nt][3]));
    }
    ml0 = fmaxf(ml0, __shfl_xor_sync(0xffffffffu, ml0, 1));
    ml0 = fmaxf(ml0, __shfl_xor_sync(0xffffffffu, ml0, 2));
    ml1 = fmaxf(ml1, __shfl_xor_sync(0xffffffffu, ml1, 1));
    ml1 = fmaxf(ml1, __shfl_xor_sync(0xffffffffu, ml1, 2));
    float ps0 = 0.f, ps1 = 0.f;
    uint32_t pa[4][4];
#pragma unroll
    for (int nt = 0; nt < 8; nt++) {
        float pp0 = fexp(cs[nt][0] - ml0);
        float pp1 = fexp(cs[nt][1] - ml0);
        float pp2 = fexp(cs[nt][2] - ml1);
        float pp3 = fexp(cs[nt][3] - ml1);
        ps0 += pp0 + pp1; ps1 += pp2 + pp3;
        pa[nt >> 1][(nt & 1) * 2 + 0] = packh2(pp0, pp1);
        pa[nt >> 1][(nt & 1) * 2 + 1] = packh2(pp2, pp3);
    }
    ps0 += __shfl_xor_sync(0xffffffffu, ps0, 1);
    ps0 += __shfl_xor_sync(0xffffffffu, ps0, 2);
    ps1 += __shfl_xor_sync(0xffffffffu, ps1, 1);
    ps1 += __shfl_xor_sync(0xffffffffu, ps1, 2);

    // acc = P V
    float o[8][4];
#pragma unroll
    for (int nt = 0; nt < 8; nt++)
#pragma unroll
        for (int e = 0; e < 4; e++) o[nt][e] = 0.f;
#pragma unroll
    for (int kk = 0; kk < 4; kk++) {
#pragma unroll
        for (int g4 = 0; g4 < 4; g4++) {
            uint32_t r0, r1, r2, r3;
            int key = kk * 16 + l8 + lb * 8;
            int dim = g4 * 16 + lh * 8;
            LDSM_X4_T(r0, r1, r2, r3, vbuf + (uint32_t)(key * (KSTR * 2) + dim * 2));
            MMA_F16(o[2 * g4],     pa[kk], r0, r1);
            MMA_F16(o[2 * g4 + 1], pa[kk], r2, r3);
        }
    }

    // write partials: pid = split*2 + kh
    const int pid = split * 2 + kh;
#pragma unroll
    for (int e = 0; e < 2; e++) {
        const int grow = wr * 16 + lr + 8 * e;
        const size_t idx = (bh * GG + grow) * 64 + pid;
        if (lc == 0) {
            g_pm[idx] = e ? ml1 : ml0;
            g_pl[idx] = e ? ps1 : ps0;
        }
        float* ap = g_pacc + idx * 64;
#pragma unroll
        for (int nt = 0; nt < 8; nt++)
            *(float2*)&ap[nt * 8 + 2 * lc] = make_float2(o[nt][2 * e], o[nt][2 * e + 1]);
    }
}

__global__ void gattn_combine_kernel(void)
{
    const int rid = blockIdx.x * blockDim.x + threadIdx.x;
    if (rid >= BB * HH * GG) return;
    float M = -1e30f;
    for (int p = 0; p < 64; p++) M = fmaxf(M, g_pm[(size_t)rid * 64 + p]);
    float L = 0.f;
    float acc[64];
#pragma unroll
    for (int d = 0; d < 64; d++) acc[d] = 0.f;
    for (int p = 0; p < 64; p++) {
        const float w = fexp(g_pm[(size_t)rid * 64 + p] - M);
        L += g_pl[(size_t)rid * 64 + p] * w;
        const float* ap = g_pacc + ((size_t)rid * 64 + p) * 64;
#pragma unroll
        for (int d = 0; d < 64; d += 4) {
            float4 a4 = *(const float4*)(ap + d);
            acc[d]   += w * a4.x;
            acc[d+1] += w * a4.y;
            acc[d+2] += w * a4.z;
            acc[d+3] += w * a4.w;
        }
    }
    const float inv = 1.f / L;
    const int bh = rid >> 6, g = rid & 63;
    __half* orow = g_attnh + ((size_t)bh * SS + g) * 64;
#pragma unroll
    for (int d = 0; d < 64; d += 2)
        *(uint32_t*)&orow[d] = packh2(acc[d] * inv, acc[d + 1] * inv);
}

// ---------------- launcher ----------------
extern "C" void kernel_launch(void* const* d_in, const int* in_sizes, int n_in,
                              void* d_out, int out_size)
{
    (void)in_sizes; (void)n_in; (void)out_size;
    const float* query = (const float*)d_in[0];
    const int*   mask  = (const int*)d_in[1];
    const float* Wq  = (const float*)d_in[2];
    const float* bq  = (const float*)d_in[3];
    const float* Wk  = (const float*)d_in[4];
    const float* bk  = (const float*)d_in[5];
    const float* Wv  = (const float*)d_in[6];
    const float* bv  = (const float*)d_in[7];
    const float* Wqg = (const float*)d_in[8];
    const float* bqg = (const float*)d_in[9];
    const float* Wkg = (const float*)d_in[10];
    const float* bkg = (const float*)d_in[11];
    const float* Wvg = (const float*)d_in[12];
    const float* bvg = (const float*)d_in[13];
    const float* Wo  = (const float*)d_in[14];
    const float* bo  = (const float*)d_in[15];
    float* out = (float*)d_out;

    __half *qb, *kb, *vb, *kgb, *vgb, *qgb;
    cudaGetSymbolAddress((void**)&qb,  g_qh);
    cudaGetSymbolAddress((void**)&kb,  g_kh);
    cudaGetSymbolAddress((void**)&vb,  g_vh);
    cudaGetSymbolAddress((void**)&kgb, g_kgh);
    cudaGetSymbolAddress((void**)&vgb, g_vgh);
    cudaGetSymbolAddress((void**)&qgb, g_qgh);

    // launch 0: weight transposes (wt: 0=q 1=k 2=v 3=kg 4=vg 5=qg 6=o)
    W7 w7;
    w7.w[0] = Wq; w7.w[1] = Wk; w7.w[2] = Wv; w7.w[3] = Wkg;
    w7.w[4] = Wvg; w7.w[5] = Wqg; w7.w[6] = Wo;
    k_wt_all<<<dim3(24, 24, 7), dim3(32, 8)>>>(w7);

    // launch 1: input transpose (fp32 -> fp16, (S,B,D)->(B,S,D))
    const int ntot = BB * SS * DD;
    k_xin<<<(ntot + 255) / 256, 256>>>(query);

    // launch 2: 6 batched GEMMs
    Gemm6 p6;
    p6.bias[0] = bq;  p6.out[0] = qb;  p6.scale[0] = 0.125f;
    p6.bias[1] = bk;  p6.out[1] = kb;  p6.scale[1] = 1.0f;
    p6.bias[2] = bv;  p6.out[2] = vb;  p6.scale[2] = 1.0f;
    p6.bias[3] = bkg; p6.out[3] = kgb; p6.scale[3] = 1.0f;
    p6.bias[4] = bvg; p6.out[4] = vgb; p6.scale[4] = 1.0f;
    p6.bias[5] = bqg; p6.out[5] = qgb; p6.scale[5] = 0.125f;
    mma_gemm6<<<dim3(6, 64, 6), 256>>>(p6);

    // launch 3: tensor-core local attention (profile slot)
    local_attn_tc<<<dim3(NCC * 2, HH, BB), 256>>>(mask);

    // launch 4,5: global attention
    gattn_part_tc<<<dim3(32, HH, BB), 256>>>(mask);
    gattn_combine_kernel<<<(BB * HH * GG + 255) / 256, 256>>>();

    // launch 6,7: output transpose + final GEMM
    k_xattn<<<(ntot / 2 + 255) / 256, 256>>>();
    mma_gemm_out<<<dim3(6, 64), 256>>>(bo, out);
}

// round 7
// speedup vs baseline: 6.8445x; 1.0326x over previous
#include <cuda_runtime.h>
#include <cuda_fp16.h>
#include <math.h>
#include <cstdint>

// Problem constants
#define BB 2
#define SS 4096
#define DD 768
#define HH 12
#define GG 64
#define HD 64
#define WW 256
#define NCC 16
#define NHEADS_S ((size_t)BB * HH * SS * HD)   // 6291456
#define QSCALE (0.125f * 1.4426950408889634f)  // fold log2e: softmax in exp2 domain

// ---------------- scratch (static device globals; no allocation) ----------------
__device__ __half g_xh  [(size_t)BB * SS * DD];      // x (B,S,D) fp16
__device__ __half g_wth [7][(size_t)DD * DD];        // W^T fp16
__device__ __half g_qh  [NHEADS_S];                  // [b][h][s][hd], scaled by QSCALE
__device__ __half g_kh  [NHEADS_S];
__device__ __half g_vh  [NHEADS_S];
__device__ __half g_kgh [NHEADS_S];
__device__ __half g_vgh [NHEADS_S];
__device__ __half g_qgh [(size_t)BB * HH * GG * HD];
__device__ __half g_xatth[(size_t)BB * SS * DD];     // attention out, row-major (b,s,d)
__device__ float g_pm   [(size_t)BB * HH * GG * 64];
__device__ float g_pl   [(size_t)BB * HH * GG * 64];
__device__ float g_pacc [(size_t)BB * HH * GG * 64 * HD];

// ---------------- helpers ----------------
__device__ __forceinline__ uint32_t smem_u32(const void* p) {
    uint32_t a;
    asm("{ .reg .u64 t; cvta.to.shared.u64 t, %1; cvt.u32.u64 %0, t; }" : "=r"(a) : "l"(p));
    return a;
}
__device__ __forceinline__ uint32_t packh2(float a, float b) {
    __half2 h = __floats2half2_rn(a, b);
    return *reinterpret_cast<uint32_t*>(&h);
}
// 2^x on the FMA pipe (scores already in log2 domain)
__device__ __forceinline__ float fexp2(float x) {
    float t = fmaxf(x, -126.0f);
    float fi = floorf(t);
    float f = t - fi;
    float p = 1.5418e-4f;
    p = fmaf(p, f, 1.3333558146e-3f);
    p = fmaf(p, f, 9.6181291108e-3f);
    p = fmaf(p, f, 5.5504108664e-2f);
    p = fmaf(p, f, 2.4022650696e-1f);
    p = fmaf(p, f, 6.9314718056e-1f);
    p = fmaf(p, f, 1.0f);
    return __int_as_float(((int)fi + 127) << 23) * p;
}
#define CP_ASYNC16(saddr, gptr) \
    asm volatile("cp.async.cg.shared.global [%0], [%1], 16;" :: "r"(saddr), "l"(gptr))
#define CP_COMMIT() asm volatile("cp.async.commit_group;" ::: "memory")
#define CP_WAIT(N)  asm volatile("cp.async.wait_group %0;" :: "n"(N) : "memory")

#define MMA_F16(d, a, b0v, b1v) \
    asm volatile( \
        "mma.sync.aligned.m16n8k16.row.col.f32.f16.f16.f32 " \
        "{%0,%1,%2,%3}, {%4,%5,%6,%7}, {%8,%9}, {%0,%1,%2,%3};" \
        : "+f"((d)[0]), "+f"((d)[1]), "+f"((d)[2]), "+f"((d)[3]) \
        : "r"((a)[0]), "r"((a)[1]), "r"((a)[2]), "r"((a)[3]), \
          "r"(b0v), "r"(b1v))

#define LDSM_X4(r0, r1, r2, r3, addr) \
    asm volatile("ldmatrix.sync.aligned.m8n8.x4.shared.b16 {%0,%1,%2,%3}, [%4];" \
                 : "=r"(r0), "=r"(r1), "=r"(r2), "=r"(r3) : "r"(addr))
#define LDSM_X4_T(r0, r1, r2, r3, addr) \
    asm volatile("ldmatrix.sync.aligned.m8n8.x4.trans.shared.b16 {%0,%1,%2,%3}, [%4];" \
                 : "=r"(r0), "=r"(r1), "=r"(r2), "=r"(r3) : "r"(addr))

// ---------------- transposes ----------------
__global__ void k_xin(const float* __restrict__ query) {
    size_t t = (size_t)blockIdx.x * blockDim.x + threadIdx.x;
    if (t >= (size_t)BB * SS * DD) return;
    int d  = (int)(t % DD);
    size_t rs = t / DD;
    int b = (int)(rs >> 12);
    int s = (int)(rs & 4095);
    g_xh[t] = __float2half_rn(query[((size_t)s * BB + b) * DD + d]);
}
struct W7 { const float* w[7]; };
__global__ void k_wt_all(W7 p) {
    __shared__ float tile[32][33];
    const float* W = p.w[blockIdx.z];
    __half* WT = g_wth[blockIdx.z];
    int x = blockIdx.x * 32 + threadIdx.x;
    int y0 = blockIdx.y * 32;
#pragma unroll
    for (int j = 0; j < 32; j += 8)
        tile[threadIdx.y + j][threadIdx.x] = W[(size_t)(y0 + threadIdx.y + j) * DD + x];
    __syncthreads();
    int kx = y0 + threadIdx.x;
#pragma unroll
    for (int j = 0; j < 32; j += 8) {
        int n = blockIdx.x * 32 + threadIdx.y + j;
        WT[(size_t)n * DD + kx] = __float2half_rn(tile[threadIdx.x][threadIdx.y + j]);
    }
}

// ---------------- fp16 mma.sync GEMM core ----------------
// CTA 128x128, 256 thr = 8 warps 2(m)x4(n), warp tile 64x32. K=768 in 24 chunks
// of 32 halves, 3-stage cp.async pipeline, ldmatrix fragment loads.
// Row stride 20 u32 = 80B (ldmatrix row addrs hit distinct banks).
#define AH 20
#define OPB (128 * AH * 4)        // 10240 per operand per stage
#define STG (2 * OPB)             // 20480
#define SMT (3 * STG)             // 61440 (dynamic)

__device__ __forceinline__ void gemm_core_h(
    const __half* __restrict__ X, const __half* __restrict__ WT,
    const float* __restrict__ bias, float* __restrict__ OutF, __half* __restrict__ OutH,
    int in_mode, int out_mode, float scale, char* smem, int m0, int n0)
{
    const uint32_t sbase = smem_u32(smem);
    const int tid = threadIdx.x;
    const int wid = tid >> 5, lane = tid & 31;
    const int wm = (wid >> 2) * 64;
    const int wn = (wid & 3) * 32;
    const int lr = lane >> 2;
    const int lc = lane & 3;
    const int l16 = lane & 15, lh = lane >> 4;

    const __half* arow[2];
    const __half* brow[2];
    uint32_t dsto[2];
#pragma unroll
    for (int i = 0; i < 2; i++) {
        int li = i * 256 + tid;
        int row = li >> 2, col4 = li & 3;
        int gr = m0 + row;
        int grow = (in_mode == 0) ? gr : ((gr >> 6) * 4096 + (gr & 63));
        arow[i] = X  + (size_t)grow * 768 + col4 * 8;
        brow[i] = WT + (size_t)(n0 + row) * 768 + col4 * 8;
        dsto[i] = (uint32_t)(row * 80 + col4 * 16);
    }

    float acc[4][4][4];
#pragma unroll
    for (int mt = 0; mt < 4; mt++)
#pragma unroll
        for (int nt = 0; nt < 4; nt++)
#pragma unroll
            for (int e = 0; e < 4; e++) acc[mt][nt][e] = 0.f;

    // issue chunk cc into stage cc%3
    auto issue = [&](int cc) {
        const int kn = cc * 32;
        const uint32_t st = (uint32_t)(cc % 3) * STG;
        uint32_t sa = sbase + st, sb = sbase + st + OPB;
#pragma unroll
        for (int i = 0; i < 2; i++) {
            CP_ASYNC16(sa + dsto[i], arow[i] + kn);
            CP_ASYNC16(sb + dsto[i], brow[i] + kn);
        }
        CP_COMMIT();
    };

    issue(0);
    issue(1);

    for (int c = 0; c < 24; c++) {
        CP_WAIT(1);
        __syncthreads();
        if (c + 2 < 24) issue(c + 2);     // stage (c+2)%3 == (c-1)%3: safe post-barrier

        const uint32_t st = (uint32_t)(c % 3) * STG;
        const uint32_t abase = sbase + st;
        const uint32_t bbase = abase + OPB;

#pragma unroll
        for (int ks = 0; ks < 2; ks++) {
            const uint32_t koff = (uint32_t)(ks * 16 + lh * 8) * 2;
            uint32_t af[4][4];
#pragma unroll
            for (int mt = 0; mt < 4; mt++)
                LDSM_X4(af[mt][0], af[mt][1], af[mt][2], af[mt][3],
                        abase + (uint32_t)(wm + mt * 16 + l16) * 80 + koff);
            uint32_t bf[2][4];
#pragma unroll
            for (int g2 = 0; g2 < 2; g2++)
                LDSM_X4(bf[g2][0], bf[g2][1], bf[g2][2], bf[g2][3],
                        bbase + (uint32_t)(wn + g2 * 16 + l16) * 80 + koff);
#pragma unroll
            for (int mt = 0; mt < 4; mt++)
#pragma unroll
                for (int g2 = 0; g2 < 2; g2++) {
                    MMA_F16(acc[mt][2 * g2],     af[mt], bf[g2][0], bf[g2][2]);
                    MMA_F16(acc[mt][2 * g2 + 1], af[mt], bf[g2][1], bf[g2][3]);
                }
        }
    }

#pragma unroll
    for (int mt = 0; mt < 4; mt++) {
#pragma unroll
        for (int half = 0; half < 2; half++) {
            const int rr = m0 + wm + mt * 16 + lr + half * 8;
#pragma unroll
            for (int nt = 0; nt < 4; nt++) {
                const int nn = n0 + wn + nt * 8 + lc * 2;
                float v0 = (acc[mt][nt][half * 2 + 0] + bias[nn])     * scale;
                float v1 = (acc[mt][nt][half * 2 + 1] + bias[nn + 1]) * scale;
                if (out_mode == 1) {
                    int bb = rr >> 12, ss = rr & 4095;
                    *(float2*)(OutF + ((size_t)ss * BB + bb) * DD + nn) = make_float2(v0, v1);
                } else if (out_mode == 0) {
                    int bb = rr >> 12, ss = rr & 4095;
                    int h = nn >> 6, hd0 = nn & 63;
                    *(uint32_t*)(OutH + ((((size_t)bb * HH + h) * SS + ss) * 64 + hd0)) = packh2(v0, v1);
                } else {
                    int bb = rr >> 6, gg2 = rr & 63;
                    int h = nn >> 6, hd0 = nn & 63;
                    *(uint32_t*)(OutH + ((((size_t)bb * HH + h) * GG + gg2) * 64 + hd0)) = packh2(v0, v1);
                }
            }
        }
    }
}

struct Gemm6 { const float* bias[6]; __half* out[6]; float scale[6]; };
__global__ __launch_bounds__(256, 2)
void mma_gemm6(Gemm6 p)
{
    extern __shared__ char smem[];
    const int z = blockIdx.z;
    if (z == 5) {
        if (blockIdx.y != 0) return;
        gemm_core_h(g_xh, g_wth[5], p.bias[5], nullptr, p.out[5], 1, 2, p.scale[5], smem,
                    0, blockIdx.x * 128);
    } else {
        gemm_core_h(g_xh, g_wth[z], p.bias[z], nullptr, p.out[z], 0, 0, p.scale[z], smem,
                    blockIdx.y * 128, blockIdx.x * 128);
    }
}
__global__ __launch_bounds__(256, 2)
void mma_gemm_out(const float* __restrict__ bias, float* __restrict__ Out)
{
    extern __shared__ char smem[];
    gemm_core_h(g_xatth, g_wth[6], bias, Out, nullptr, 0, 1, 1.0f, smem,
                blockIdx.y * 128, blockIdx.x * 128);
}

// ---------------- fp16 tensor-core local windowed attention ----------------
// grid (NC*2, H, B), 256 thr = 8 warps; 11 tiles of 64 keys (1 global + 10 band),
// double-buffered cp.async; ldmatrix B-frags; P in registers; softmax in exp2 domain.
// Per-tile warp-uniform mask skip: interior+clean tiles bypass all predicate ALU.
#define KSTR 72
__global__ __launch_bounds__(256, 2)
void local_attn_tc(const int* __restrict__ mask)
{
    __shared__ __align__(16) __half ksm[2][64 * KSTR];
    __shared__ __align__(16) __half vsm[2][64 * KSTR];
    __shared__ unsigned char okarr[704];
    __shared__ int tclean[10];

    const int c = blockIdx.x >> 1, h = blockIdx.y, b = blockIdx.z;
    const int rhalf = blockIdx.x & 1;
    const int i0 = rhalf * 128;
    const int tid = threadIdx.x, wid = tid >> 5, lane = tid & 31;
    const int lr = lane >> 2, lc = lane & 3;
    const int l8 = lane & 7, lb = (lane >> 3) & 1, lh = lane >> 4;
    const size_t bh = (size_t)b * HH + h;
    const int s0 = c * WW + i0;
    const int tlo = rhalf * 2;
    const int bandlo = (c - 1) * WW + tlo * 64;

    // ok flags: [0,64) global keys (always ok), [64,704) band positions
    for (int j = tid; j < 704; j += 256) {
        int ok;
        if (j < 64) ok = 1;
        else {
            int p = bandlo + (j - 64);
            ok = (p >= 0 && p < SS && mask[b * SS + p] == 0) ? 1 : 0;
        }
        okarr[j] = (unsigned char)ok;
    }
    __syncthreads();
    if (tid < 10) {
        const uint32_t* w = (const uint32_t*)(okarr + 64 + tid * 64);
        uint32_t allv = 0xFFFFFFFFu;
#pragma unroll
        for (int q4 = 0; q4 < 16; q4++) allv &= w[q4];
        tclean[tid] = (allv == 0x01010101u) ? 1 : 0;
    }

    // Q fragments (q pre-scaled by 0.125*log2e)
    uint32_t qa[4][4];
    {
        const __half* qb2 = g_qh + (bh * SS + s0 + wid * 16) * 64;
#pragma unroll
        for (int kk = 0; kk < 4; kk++) {
            qa[kk][0] = *(const uint32_t*)&qb2[(lr)     * 64 + kk * 16 + 2 * lc];
            qa[kk][1] = *(const uint32_t*)&qb2[(lr + 8) * 64 + kk * 16 + 2 * lc];
            qa[kk][2] = *(const uint32_t*)&qb2[(lr)     * 64 + kk * 16 + 8 + 2 * lc];
            qa[kk][3] = *(const uint32_t*)&qb2[(lr + 8) * 64 + kk * 16 + 8 + 2 * lc];
        }
    }

    float o[8][4];
#pragma unroll
    for (int nt = 0; nt < 8; nt++)
#pragma unroll
        for (int e = 0; e < 4; e++) o[nt][e] = 0.f;
    float mrun[2] = { -1e30f, -1e30f };
    float lrun[2] = { 0.f, 0.f };

    const __half* kbase = g_kh + bh * SS * 64;
    const __half* vbase = g_vh + bh * SS * 64;
    const int wbase = i0 + wid * 16;       // warp q-row base (uniform)
    const int irelA = wbase + lr;
    const int irelB = irelA + 8;

    auto issue_tile = [&](int ti, int buf) {
        const int pbase = (ti == 0) ? 0 : bandlo + (ti - 1) * 64;
        const uint32_t kdst = smem_u32(&ksm[buf][0]);
        const uint32_t vdst = smem_u32(&vsm[buf][0]);
#pragma unroll
        for (int i = 0; i < 4; i++) {
            int li = i * 256 + tid;
            int op = li >> 9;
            int rem = li & 511;
            int row = rem >> 3, ch = rem & 7;
            int p = pbase + row;
            p = (p < 0) ? 0 : ((p >= SS) ? SS - 1 : p);
            const __half* src = (op ? vbase : kbase) + (size_t)p * 64 + ch * 8;
            uint32_t dst = (op ? vdst : kdst) + (uint32_t)(row * (KSTR * 2) + ch * 16);
            CP_ASYNC16(dst, src);
        }
        CP_COMMIT();
    };

    issue_tile(0, 0);

    for (int ti = 0; ti < 11; ti++) {
        if (ti < 10) { issue_tile(ti + 1, (ti + 1) & 1); CP_WAIT(1); }
        else         { CP_WAIT(0); }
        __syncthreads();

        const uint32_t kbuf = smem_u32(&ksm[ti & 1][0]);
        const uint32_t vbuf = smem_u32(&vsm[ti & 1][0]);

        // S = Q K^T
        float cs[8][4];
#pragma unroll
        for (int nt = 0; nt < 8; nt++)
#pragma unroll
            for (int e = 0; e < 4; e++) cs[nt][e] = 0.f;
#pragma unroll
        for (int kk = 0; kk < 4; kk++) {
#pragma unroll
            for (int g4 = 0; g4 < 4; g4++) {
                uint32_t r0, r1, r2, r3;
                int key = g4 * 16 + l8 + lb * 8;
                int dim = kk * 16 + lh * 8;
                LDSM_X4(r0, r1, r2, r3, kbuf + (uint32_t)(key * (KSTR * 2) + dim * 2));
                MMA_F16(cs[2 * g4],     qa[kk], r0, r2);
                MMA_F16(cs[2 * g4 + 1], qa[kk], r1, r3);
            }
        }

        // masking — only boundary/unclean band tiles (warp-uniform test)
        if (ti > 0) {
            const int jbase = (tlo + ti - 1) * 64;
            const bool interior = (tclean[ti - 1] != 0) &&
                                  (jbase >= wbase + 15) &&
                                  (jbase + 63 <= wbase + 2 * WW);
            if (!interior) {
                const unsigned char* okp = okarr + 64 + (ti - 1) * 64;
#pragma unroll
                for (int nt = 0; nt < 8; nt++) {
                    int jl = nt * 8 + 2 * lc;
                    int j = jbase + jl;
                    bool o0 = okp[jl] != 0, o1 = okp[jl + 1] != 0;
                    if (!(o0 && j     >= irelA && j     <= irelA + 512)) cs[nt][0] = -1e30f;
                    if (!(o1 && j + 1 >= irelA && j + 1 <= irelA + 512)) cs[nt][1] = -1e30f;
                    if (!(o0 && j     >= irelB && j     <= irelB + 512)) cs[nt][2] = -1e30f;
                    if (!(o1 && j + 1 >= irelB && j + 1 <= irelB + 512)) cs[nt][3] = -1e30f;
                }
            }
        }

        // online softmax (exp2 domain)
        float ml0 = -1e30f, ml1 = -1e30f;
#pragma unroll
        for (int nt = 0; nt < 8; nt++) {
            ml0 = fmaxf(ml0, fmaxf(cs[nt][0], cs[nt][1]));
            ml1 = fmaxf(ml1, fmaxf(cs[nt][2], cs[nt][3]));
        }
        ml0 = fmaxf(ml0, __shfl_xor_sync(0xffffffffu, ml0, 1));
        ml0 = fmaxf(ml0, __shfl_xor_sync(0xffffffffu, ml0, 2));
        ml1 = fmaxf(ml1, __shfl_xor_sync(0xffffffffu, ml1, 1));
        ml1 = fmaxf(ml1, __shfl_xor_sync(0xffffffffu, ml1, 2));
        float mn0 = fmaxf(mrun[0], ml0), mn1 = fmaxf(mrun[1], ml1);
        float corr0 = fexp2(mrun[0] - mn0), corr1 = fexp2(mrun[1] - mn1);
        mrun[0] = mn0; mrun[1] = mn1;
        float ps0 = 0.f, ps1 = 0.f;
        uint32_t pa[4][4];
#pragma unroll
        for (int nt = 0; nt < 8; nt++) {
            float p0 = fexp2(cs[nt][0] - mn0);
            float p1 = fexp2(cs[nt][1] - mn0);
            float p2 = fexp2(cs[nt][2] - mn1);
            float p3 = fexp2(cs[nt][3] - mn1);
            ps0 += p0 + p1; ps1 += p2 + p3;
            pa[nt >> 1][(nt & 1) * 2 + 0] = packh2(p0, p1);
            pa[nt >> 1][(nt & 1) * 2 + 1] = packh2(p2, p3);
            o[nt][0] *= corr0; o[nt][1] *= corr0;
            o[nt][2] *= corr1; o[nt][3] *= corr1;
        }
        lrun[0] = lrun[0] * corr0 + ps0;
        lrun[1] = lrun[1] * corr1 + ps1;

        // O += P V
#pragma unroll
        for (int kk = 0; kk < 4; kk++) {
#pragma unroll
            for (int g4 = 0; g4 < 4; g4++) {
                uint32_t r0, r1, r2, r3;
                int key = kk * 16 + l8 + lb * 8;
                int dim = g4 * 16 + lh * 8;
                LDSM_X4_T(r0, r1, r2, r3, vbuf + (uint32_t)(key * (KSTR * 2) + dim * 2));
                MMA_F16(o[2 * g4],     pa[kk], r0, r1);
                MMA_F16(o[2 * g4 + 1], pa[kk], r2, r3);
            }
        }
        __syncthreads();
    }

    // normalize + write directly to row-major g_xatth (b, s, h*64+hd)
#pragma unroll
    for (int e = 0; e < 2; e++) {
        float ll = lrun[e];
        ll += __shfl_xor_sync(0xffffffffu, ll, 1);
        ll += __shfl_xor_sync(0xffffffffu, ll, 2);
        const float inv = 1.f / ll;
        const int srow = s0 + wid * 16 + lr + 8 * e;
        __half* orow = g_xatth + ((size_t)b * SS + srow) * DD + h * 64;
#pragma unroll
        for (int nt = 0; nt < 8; nt++)
            *(uint32_t*)&orow[nt * 8 + 2 * lc] =
                packh2(o[nt][2 * e] * inv, o[nt][2 * e + 1] * inv);
    }
}

// ---------------- fp16 tensor-core global attention (split-K partials) ----------------
__global__ __launch_bounds__(256, 2)
void gattn_part_tc(const int* __restrict__ mask)
{
    __shared__ __align__(16) __half kgs[128 * KSTR];
    __shared__ __align__(16) __half vgs[128 * KSTR];
    __shared__ unsigned char okg[128];

    const int split = blockIdx.x, h = blockIdx.y, b = blockIdx.z;
    const int tid = threadIdx.x, wid = tid >> 5, lane = tid & 31;
    const int lr = lane >> 2, lc = lane & 3;
    const int l8 = lane & 7, lb = (lane >> 3) & 1, lh = lane >> 4;
    const size_t bh = (size_t)b * HH + h;
    const int wr = wid & 3, kh = wid >> 2;
    const int p0 = split * 128;

    {
        const __half* kb2 = g_kgh + (bh * SS + p0) * 64;
        const __half* vb2 = g_vgh + (bh * SS + p0) * 64;
        const uint32_t kdst = smem_u32(kgs);
        const uint32_t vdst = smem_u32(vgs);
#pragma unroll
        for (int i = 0; i < 8; i++) {
            int li = i * 256 + tid;
            int op = li >> 10;
            int rem = li & 1023;
            int row = rem >> 3, ch = rem & 7;
            const __half* src = (op ? vb2 : kb2) + (size_t)row * 64 + ch * 8;
            uint32_t dst = (op ? vdst : kdst) + (uint32_t)(row * (KSTR * 2) + ch * 16);
            CP_ASYNC16(dst, src);
        }
        CP_COMMIT();
        if (tid < 128) okg[tid] = (mask[b * SS + p0 + tid] <= 0) ? 1 : 0;
        CP_WAIT(0);
        __syncthreads();
    }

    uint32_t qa[4][4];
    {
        const __half* qb2 = g_qgh + (bh * GG + wr * 16) * 64;
#pragma unroll
        for (int kk = 0; kk < 4; kk++) {
            qa[kk][0] = *(const uint32_t*)&qb2[(lr)     * 64 + kk * 16 + 2 * lc];
            qa[kk][1] = *(const uint32_t*)&qb2[(lr + 8) * 64 + kk * 16 + 2 * lc];
            qa[kk][2] = *(const uint32_t*)&qb2[(lr)     * 64 + kk * 16 + 8 + 2 * lc];
            qa[kk][3] = *(const uint32_t*)&qb2[(lr + 8) * 64 + kk * 16 + 8 + 2 * lc];
        }
    }

    const uint32_t kbuf = smem_u32(kgs) + (uint32_t)(kh * 64 * KSTR * 2);
    const uint32_t vbuf = smem_u32(vgs) + (uint32_t)(kh * 64 * KSTR * 2);

    float cs[8][4];
#pragma unroll
    for (int nt = 0; nt < 8; nt++)
#pragma unroll
        for (int e = 0; e < 4; e++) cs[nt][e] = 0.f;
#pragma unroll
    for (int kk = 0; kk < 4; kk++) {
#pragma unroll
        for (int g4 = 0; g4 < 4; g4++) {
            uint32_t r0, r1, r2, r3;
            int key = g4 * 16 + l8 + lb * 8;
            int dim = kk * 16 + lh * 8;
            LDSM_X4(r0, r1, r2, r3, kbuf + (uint32_t)(key * (KSTR * 2) + dim * 2));
            MMA_F16(cs[2 * g4],     qa[kk], r0, r2);
            MMA_F16(cs[2 * g4 + 1], qa[kk], r1, r3);
        }
    }
#pragma unroll
    for (int nt = 0; nt < 8; nt++) {
        int jl = kh * 64 + nt * 8 + 2 * lc;
        if (!okg[jl])     { cs[nt][0] = -1e30f; cs[nt][2] = -1e30f; }
        if (!okg[jl + 1]) { cs[nt][1] = -1e30f; cs[nt][3] = -1e30f; }
    }
    float ml0 = -1e30f, ml1 = -1e30f;
#pragma unroll
    for (int nt = 0; nt < 8; nt++) {
        ml0 = fmaxf(ml0, fmaxf(cs[nt][0], cs[nt][1]));
        ml1 = fmaxf(ml1, fmaxf(cs[nt][2], cs[nt][3]));
    }
    ml0 = fmaxf(ml0, __shfl_xor_sync(0xffffffffu, ml0, 1));
    ml0 = fmaxf(ml0, __shfl_xor_sync(0xffffffffu, ml0, 2));
    ml1 = fmaxf(ml1, __shfl_xor_sync(0xffffffffu, ml1, 1));
    ml1 = fmaxf(ml1, __shfl_xor_sync(0xffffffffu, ml1, 2));
    float ps0 = 0.f, ps1 = 0.f;
    uint32_t pa[4][4];
#pragma unroll
    for (int nt = 0; nt < 8; nt++) {
        float pp0 = fexp2(cs[nt][0] - ml0);
        float pp1 = fexp2(cs[nt][1] - ml0);
        float pp2 = fexp2(cs[nt][2] - ml1);
        float pp3 = fexp2(cs[nt][3] - ml1);
        ps0 += pp0 + pp1; ps1 += pp2 + pp3;
        pa[nt >> 1][(nt & 1) * 2 + 0] = packh2(pp0, pp1);
        pa[nt >> 1][(nt & 1) * 2 + 1] = packh2(pp2, pp3);
    }
    ps0 += __shfl_xor_sync(0xffffffffu, ps0, 1);
    ps0 += __shfl_xor_sync(0xffffffffu, ps0, 2);
    ps1 += __shfl_xor_sync(0xffffffffu, ps1, 1);
    ps1 += __shfl_xor_sync(0xffffffffu, ps1, 2);

    float o[8][4];
#pragma unroll
    for (int nt = 0; nt < 8; nt++)
#pragma unroll
        for (int e = 0; e < 4; e++) o[nt][e] = 0.f;
#pragma unroll
    for (int kk = 0; kk < 4; kk++) {
#pragma unroll
        for (int g4 = 0; g4 < 4; g4++) {
            uint32_t r0, r1, r2, r3;
            int key = kk * 16 + l8 + lb * 8;
            int dim = g4 * 16 + lh * 8;
            LDSM_X4_T(r0, r1, r2, r3, vbuf + (uint32_t)(key * (KSTR * 2) + dim * 2));
            MMA_F16(o[2 * g4],     pa[kk], r0, r1);
            MMA_F16(o[2 * g4 + 1], pa[kk], r2, r3);
        }
    }

    const int pid = split * 2 + kh;
#pragma unroll
    for (int e = 0; e < 2; e++) {
        const int grow = wr * 16 + lr + 8 * e;
        const size_t idx = (bh * GG + grow) * 64 + pid;
        if (lc == 0) {
            g_pm[idx] = e ? ml1 : ml0;
            g_pl[idx] = e ? ps1 : ps0;
        }
        float* ap = g_pacc + idx * 64;
#pragma unroll
        for (int nt = 0; nt < 8; nt++)
            *(float2*)&ap[nt * 8 + 2 * lc] = make_float2(o[nt][2 * e], o[nt][2 * e + 1]);
    }
}

__global__ void gattn_combine_kernel(void)
{
    const int rid = blockIdx.x * blockDim.x + threadIdx.x;
    if (rid >= BB * HH * GG) return;
    float M = -1e30f;
    for (int p = 0; p < 64; p++) M = fmaxf(M, g_pm[(size_t)rid * 64 + p]);
    float L = 0.f;
    float acc[64];
#pragma unroll
    for (int d = 0; d < 64; d++) acc[d] = 0.f;
    for (int p = 0; p < 64; p++) {
        const float w = fexp2(g_pm[(size_t)rid * 64 + p] - M);
        L += g_pl[(size_t)rid * 64 + p] * w;
        const float* ap = g_pacc + ((size_t)rid * 64 + p) * 64;
#pragma unroll
        for (int d = 0; d < 64; d += 4) {
            float4 a4 = *(const float4*)(ap + d);
            acc[d]   += w * a4.x;
            acc[d+1] += w * a4.y;
            acc[d+2] += w * a4.z;
            acc[d+3] += w * a4.w;
        }
    }
    const float inv = 1.f / L;
    const int bh = rid >> 6, g = rid & 63;
    const int b = bh / HH, h = bh % HH;
    __half* orow = g_xatth + ((size_t)b * SS + g) * DD + h * 64;
#pragma unroll
    for (int d = 0; d < 64; d += 2)
        *(uint32_t*)&orow[d] = packh2(acc[d] * inv, acc[d + 1] * inv);
}

// ---------------- launcher ----------------
extern "C" void kernel_launch(void* const* d_in, const int* in_sizes, int n_in,
                              void* d_out, int out_size)
{
    (void)in_sizes; (void)n_in; (void)out_size;
    const float* query = (const float*)d_in[0];
    const int*   mask  = (const int*)d_in[1];
    const float* Wq  = (const float*)d_in[2];
    const float* bq  = (const float*)d_in[3];
    const float* Wk  = (const float*)d_in[4];
    const float* bk  = (const float*)d_in[5];
    const float* Wv  = (const float*)d_in[6];
    const float* bv  = (const float*)d_in[7];
    const float* Wqg = (const float*)d_in[8];
    const float* bqg = (const float*)d_in[9];
    const float* Wkg = (const float*)d_in[10];
    const float* bkg = (const float*)d_in[11];
    const float* Wvg = (const float*)d_in[12];
    const float* bvg = (const float*)d_in[13];
    const float* Wo  = (const float*)d_in[14];
    const float* bo  = (const float*)d_in[15];
    float* out = (float*)d_out;

    __half *qb, *kb, *vb, *kgb, *vgb, *qgb;
    cudaGetSymbolAddress((void**)&qb,  g_qh);
    cudaGetSymbolAddress((void**)&kb,  g_kh);
    cudaGetSymbolAddress((void**)&vb,  g_vh);
    cudaGetSymbolAddress((void**)&kgb, g_kgh);
    cudaGetSymbolAddress((void**)&vgb, g_vgh);
    cudaGetSymbolAddress((void**)&qgb, g_qgh);

    cudaFuncSetAttribute(mma_gemm6,    cudaFuncAttributeMaxDynamicSharedMemorySize, SMT);
    cudaFuncSetAttribute(mma_gemm_out, cudaFuncAttributeMaxDynamicSharedMemorySize, SMT);

    // launch 0: weight transposes (wt: 0=q 1=k 2=v 3=kg 4=vg 5=qg 6=o)
    W7 w7;
    w7.w[0] = Wq; w7.w[1] = Wk; w7.w[2] = Wv; w7.w[3] = Wkg;
    w7.w[4] = Wvg; w7.w[5] = Wqg; w7.w[6] = Wo;
    k_wt_all<<<dim3(24, 24, 7), dim3(32, 8)>>>(w7);

    // launch 1: input transpose
    const int ntot = BB * SS * DD;
    k_xin<<<(ntot + 255) / 256, 256>>>(query);

    // launch 2: 6 batched GEMMs (q/qg scaled by 0.125*log2e for exp2 softmax)
    Gemm6 p6;
    p6.bias[0] = bq;  p6.out[0] = qb;  p6.scale[0] = QSCALE;
    p6.bias[1] = bk;  p6.out[1] = kb;  p6.scale[1] = 1.0f;
    p6.bias[2] = bv;  p6.out[2] = vb;  p6.scale[2] = 1.0f;
    p6.bias[3] = bkg; p6.out[3] = kgb; p6.scale[3] = 1.0f;
    p6.bias[4] = bvg; p6.out[4] = vgb; p6.scale[4] = 1.0f;
    p6.bias[5] = bqg; p6.out[5] = qgb; p6.scale[5] = QSCALE;
    mma_gemm6<<<dim3(6, 64, 6), 256, SMT>>>(p6);

    // launch 3: tensor-core local attention (profile slot)
    local_attn_tc<<<dim3(NCC * 2, HH, BB), 256>>>(mask);

    // launch 4,5: global attention
    gattn_part_tc<<<dim3(32, HH, BB), 256>>>(mask);
    gattn_combine_kernel<<<(BB * HH * GG + 255) / 256, 256>>>();

    // launch 6: final GEMM (reads g_xatth written directly by attention kernels)
    mma_gemm_out<<<dim3(6, 64), 256, SMT>>>(bo, out);
}

// round 8
// speedup vs baseline: 6.9960x; 1.0221x over previous
#include <cuda_runtime.h>
#include <cuda_fp16.h>
#include <math.h>
#include <cstdint>

// Problem constants
#define BB 2
#define SS 4096
#define DD 768
#define HH 12
#define GG 64
#define HD 64
#define WW 256
#define NCC 16
#define NHEADS_S ((size_t)BB * HH * SS * HD)   // 6291456
#define QSCALE (0.125f * 1.4426950408889634f)  // fold log2e: softmax in exp2 domain

// ---------------- scratch (static device globals; no allocation) ----------------
__device__ __half g_xh  [(size_t)BB * SS * DD];      // x (B,S,D) fp16
__device__ __half g_wth [7][(size_t)DD * DD];        // W^T fp16
__device__ __half g_qh  [NHEADS_S];                  // [b][h][s][hd], scaled by QSCALE
__device__ __half g_kh  [NHEADS_S];
__device__ __half g_vh  [NHEADS_S];
__device__ __half g_kgh [NHEADS_S];
__device__ __half g_vgh [NHEADS_S];
__device__ __half g_qgh [(size_t)BB * HH * GG * HD];
__device__ __half g_xatth[(size_t)BB * SS * DD];     // attention out, row-major (b,s,d)
__device__ float g_pm   [(size_t)BB * HH * GG * 64];
__device__ float g_pl   [(size_t)BB * HH * GG * 64];
__device__ float g_pacc [(size_t)BB * HH * GG * 64 * HD];

// ---------------- helpers ----------------
__device__ __forceinline__ uint32_t smem_u32(const void* p) {
    uint32_t a;
    asm("{ .reg .u64 t; cvta.to.shared.u64 t, %1; cvt.u32.u64 %0, t; }" : "=r"(a) : "l"(p));
    return a;
}
__device__ __forceinline__ uint32_t packh2(float a, float b) {
    __half2 h = __floats2half2_rn(a, b);
    return *reinterpret_cast<uint32_t*>(&h);
}
// 2^x on the FMA pipe: magic round-to-nearest, degree-4 poly on [-0.5, 0.5]
__device__ __forceinline__ float fexp2(float x) {
    float t = fmaxf(x, -125.0f);
    float r = t + 12582912.0f;                 // 1.5*2^23: RN to integer
    float fi = r - 12582912.0f;
    float f = t - fi;                          // [-0.5, 0.5]
    int n = __float_as_int(r) - 0x4B400000;    // integer part (signed)
    float p = 9.61812911e-3f;
    p = fmaf(p, f, 5.55041087e-2f);
    p = fmaf(p, f, 2.40226507e-1f);
    p = fmaf(p, f, 6.93147180e-1f);
    p = fmaf(p, f, 1.0f);
    return __int_as_float((n + 127) << 23) * p;
}
#define CP_ASYNC16(saddr, gptr) \
    asm volatile("cp.async.cg.shared.global [%0], [%1], 16;" :: "r"(saddr), "l"(gptr))
#define CP_COMMIT() asm volatile("cp.async.commit_group;" ::: "memory")
#define CP_WAIT(N)  asm volatile("cp.async.wait_group %0;" :: "n"(N) : "memory")

#define MMA_F16(d, a, b0v, b1v) \
    asm volatile( \
        "mma.sync.aligned.m16n8k16.row.col.f32.f16.f16.f32 " \
        "{%0,%1,%2,%3}, {%4,%5,%6,%7}, {%8,%9}, {%0,%1,%2,%3};" \
        : "+f"((d)[0]), "+f"((d)[1]), "+f"((d)[2]), "+f"((d)[3]) \
        : "r"((a)[0]), "r"((a)[1]), "r"((a)[2]), "r"((a)[3]), \
          "r"(b0v), "r"(b1v))

#define LDSM_X4(r0, r1, r2, r3, addr) \
    asm volatile("ldmatrix.sync.aligned.m8n8.x4.shared.b16 {%0,%1,%2,%3}, [%4];" \
                 : "=r"(r0), "=r"(r1), "=r"(r2), "=r"(r3) : "r"(addr))
#define LDSM_X4_T(r0, r1, r2, r3, addr) \
    asm volatile("ldmatrix.sync.aligned.m8n8.x4.trans.shared.b16 {%0,%1,%2,%3}, [%4];" \
                 : "=r"(r0), "=r"(r1), "=r"(r2), "=r"(r3) : "r"(addr))

// ---------------- transposes ----------------
__global__ void k_xin(const float* __restrict__ query) {
    size_t t = (size_t)blockIdx.x * blockDim.x + threadIdx.x;
    if (t >= (size_t)BB * SS * DD) return;
    int d  = (int)(t % DD);
    size_t rs = t / DD;
    int b = (int)(rs >> 12);
    int s = (int)(rs & 4095);
    g_xh[t] = __float2half_rn(query[((size_t)s * BB + b) * DD + d]);
}
struct W7 { const float* w[7]; };
__global__ void k_wt_all(W7 p, int zoff) {
    __shared__ float tile[32][33];
    const int z = zoff + blockIdx.z;
    const float* W = p.w[z];
    __half* WT = g_wth[z];
    int x = blockIdx.x * 32 + threadIdx.x;
    int y0 = blockIdx.y * 32;
#pragma unroll
    for (int j = 0; j < 32; j += 8)
        tile[threadIdx.y + j][threadIdx.x] = W[(size_t)(y0 + threadIdx.y + j) * DD + x];
    __syncthreads();
    int kx = y0 + threadIdx.x;
#pragma unroll
    for (int j = 0; j < 32; j += 8) {
        int n = blockIdx.x * 32 + threadIdx.y + j;
        WT[(size_t)n * DD + kx] = __float2half_rn(tile[threadIdx.x][threadIdx.y + j]);
    }
}

// ---------------- fp16 mma.sync GEMM core ----------------
#define AH 20
#define OPB (128 * AH * 4)        // 10240 per operand per stage
#define STG (2 * OPB)             // 20480
#define SMT (3 * STG)             // 61440 (dynamic)

__device__ __forceinline__ void gemm_core_h(
    const __half* __restrict__ X, const __half* __restrict__ WT,
    const float* __restrict__ bias, float* __restrict__ OutF, __half* __restrict__ OutH,
    int in_mode, int out_mode, float scale, char* smem, int m0, int n0)
{
    const uint32_t sbase = smem_u32(smem);
    const int tid = threadIdx.x;
    const int wid = tid >> 5, lane = tid & 31;
    const int wm = (wid >> 2) * 64;
    const int wn = (wid & 3) * 32;
    const int lr = lane >> 2;
    const int lc = lane & 3;
    const int l16 = lane & 15, lh = lane >> 4;

    const __half* arow[2];
    const __half* brow[2];
    uint32_t dsto[2];
#pragma unroll
    for (int i = 0; i < 2; i++) {
        int li = i * 256 + tid;
        int row = li >> 2, col4 = li & 3;
        int gr = m0 + row;
        int grow = (in_mode == 0) ? gr : ((gr >> 6) * 4096 + (gr & 63));
        arow[i] = X  + (size_t)grow * 768 + col4 * 8;
        brow[i] = WT + (size_t)(n0 + row) * 768 + col4 * 8;
        dsto[i] = (uint32_t)(row * 80 + col4 * 16);
    }

    float acc[4][4][4];
#pragma unroll
    for (int mt = 0; mt < 4; mt++)
#pragma unroll
        for (int nt = 0; nt < 4; nt++)
#pragma unroll
            for (int e = 0; e < 4; e++) acc[mt][nt][e] = 0.f;

    auto issue = [&](int cc) {
        const int kn = cc * 32;
        const uint32_t st = (uint32_t)(cc % 3) * STG;
        uint32_t sa = sbase + st, sb = sbase + st + OPB;
#pragma unroll
        for (int i = 0; i < 2; i++) {
            CP_ASYNC16(sa + dsto[i], arow[i] + kn);
            CP_ASYNC16(sb + dsto[i], brow[i] + kn);
        }
        CP_COMMIT();
    };

    issue(0);
    issue(1);

    for (int c = 0; c < 24; c++) {
        CP_WAIT(1);
        __syncthreads();
        if (c + 2 < 24) issue(c + 2);

        const uint32_t st = (uint32_t)(c % 3) * STG;
        const uint32_t abase = sbase + st;
        const uint32_t bbase = abase + OPB;

#pragma unroll
        for (int ks = 0; ks < 2; ks++) {
            const uint32_t koff = (uint32_t)(ks * 16 + lh * 8) * 2;
            uint32_t af[4][4];
#pragma unroll
            for (int mt = 0; mt < 4; mt++)
                LDSM_X4(af[mt][0], af[mt][1], af[mt][2], af[mt][3],
                        abase + (uint32_t)(wm + mt * 16 + l16) * 80 + koff);
            uint32_t bf[2][4];
#pragma unroll
            for (int g2 = 0; g2 < 2; g2++)
                LDSM_X4(bf[g2][0], bf[g2][1], bf[g2][2], bf[g2][3],
                        bbase + (uint32_t)(wn + g2 * 16 + l16) * 80 + koff);
#pragma unroll
            for (int mt = 0; mt < 4; mt++)
#pragma unroll
                for (int g2 = 0; g2 < 2; g2++) {
                    MMA_F16(acc[mt][2 * g2],     af[mt], bf[g2][0], bf[g2][2]);
                    MMA_F16(acc[mt][2 * g2 + 1], af[mt], bf[g2][1], bf[g2][3]);
                }
        }
    }

#pragma unroll
    for (int mt = 0; mt < 4; mt++) {
#pragma unroll
        for (int half = 0; half < 2; half++) {
            const int rr = m0 + wm + mt * 16 + lr + half * 8;
#pragma unroll
            for (int nt = 0; nt < 4; nt++) {
                const int nn = n0 + wn + nt * 8 + lc * 2;
                float v0 = (acc[mt][nt][half * 2 + 0] + bias[nn])     * scale;
                float v1 = (acc[mt][nt][half * 2 + 1] + bias[nn + 1]) * scale;
                if (out_mode == 1) {
                    int bb = rr >> 12, ss = rr & 4095;
                    *(float2*)(OutF + ((size_t)ss * BB + bb) * DD + nn) = make_float2(v0, v1);
                } else if (out_mode == 0) {
                    int bb = rr >> 12, ss = rr & 4095;
                    int h = nn >> 6, hd0 = nn & 63;
                    *(uint32_t*)(OutH + ((((size_t)bb * HH + h) * SS + ss) * 64 + hd0)) = packh2(v0, v1);
                } else {
                    int bb = rr >> 6, gg2 = rr & 63;
                    int h = nn >> 6, hd0 = nn & 63;
                    *(uint32_t*)(OutH + ((((size_t)bb * HH + h) * GG + gg2) * 64 + hd0)) = packh2(v0, v1);
                }
            }
        }
    }
}

struct Gemm6 { const float* bias[6]; __half* out[6]; float scale[6]; };
__global__ __launch_bounds__(256, 2)
void mma_gemm6(Gemm6 p)
{
    extern __shared__ char smem[];
    const int z = blockIdx.z;
    if (z == 5) {
        if (blockIdx.y != 0) return;
        gemm_core_h(g_xh, g_wth[5], p.bias[5], nullptr, p.out[5], 1, 2, p.scale[5], smem,
                    0, blockIdx.x * 128);
    } else {
        gemm_core_h(g_xh, g_wth[z], p.bias[z], nullptr, p.out[z], 0, 0, p.scale[z], smem,
                    blockIdx.y * 128, blockIdx.x * 128);
    }
}
__global__ __launch_bounds__(256, 2)
void mma_gemm_out(const float* __restrict__ bias, float* __restrict__ Out)
{
    extern __shared__ char smem[];
    gemm_core_h(g_xatth, g_wth[6], bias, Out, nullptr, 0, 1, 1.0f, smem,
                blockIdx.y * 128, blockIdx.x * 128);
}

// ---------------- merged local + global attention ----------------
// grid (64, H, B): bx<32 -> local windowed (half-chunk), bx>=32 -> global split.
// Local: 11 tiles of 64 keys, 3-stage cp.async (single barrier/tile), warp-uniform
// running max (skippable rescale), exp2-domain softmax, ldmatrix B-frags.
#define KSTR 72
#define ST_KV 18432                      // per-stage K+V bytes (2 * 64*72*2)
#define L_OK  (3 * ST_KV)                // 55296: ok flags (704 B)
#define L_TCL (L_OK + 704)               // 56000: tclean int[10]
#define LA_SMEM 56320

__device__ void local_attn_body(char* sm, const int* __restrict__ mask)
{
    const uint32_t sbase = smem_u32(sm);
    unsigned char* okarr = (unsigned char*)(sm + L_OK);
    int* tclean = (int*)(sm + L_TCL);

    const int c = blockIdx.x >> 1, h = blockIdx.y, b = blockIdx.z;
    const int rhalf = blockIdx.x & 1;
    const int i0 = rhalf * 128;
    const int tid = threadIdx.x, wid = tid >> 5, lane = tid & 31;
    const int lr = lane >> 2, lc = lane & 3;
    const int l8 = lane & 7, lb = (lane >> 3) & 1, lh = lane >> 4;
    const size_t bh = (size_t)b * HH + h;
    const int s0 = c * WW + i0;
    const int tlo = rhalf * 2;
    const int bandlo = (c - 1) * WW + tlo * 64;

    // ok flags: [0,64) global keys (always ok), [64,704) band positions
    for (int j = tid; j < 704; j += 256) {
        int ok;
        if (j < 64) ok = 1;
        else {
            int p = bandlo + (j - 64);
            ok = (p >= 0 && p < SS && mask[b * SS + p] == 0) ? 1 : 0;
        }
        okarr[j] = (unsigned char)ok;
    }
    __syncthreads();
    if (tid < 10) {
        const uint32_t* w = (const uint32_t*)(okarr + 64 + tid * 64);
        uint32_t allv = 0xFFFFFFFFu;
#pragma unroll
        for (int q4 = 0; q4 < 16; q4++) allv &= w[q4];
        tclean[tid] = (allv == 0x01010101u) ? 1 : 0;
    }

    // Q fragments
    uint32_t qa[4][4];
    {
        const __half* qb2 = g_qh + (bh * SS + s0 + wid * 16) * 64;
#pragma unroll
        for (int kk = 0; kk < 4; kk++) {
            qa[kk][0] = *(const uint32_t*)&qb2[(lr)     * 64 + kk * 16 + 2 * lc];
            qa[kk][1] = *(const uint32_t*)&qb2[(lr + 8) * 64 + kk * 16 + 2 * lc];
            qa[kk][2] = *(const uint32_t*)&qb2[(lr)     * 64 + kk * 16 + 8 + 2 * lc];
            qa[kk][3] = *(const uint32_t*)&qb2[(lr + 8) * 64 + kk * 16 + 8 + 2 * lc];
        }
    }

    float o[8][4];
#pragma unroll
    for (int nt = 0; nt < 8; nt++)
#pragma unroll
        for (int e = 0; e < 4; e++) o[nt][e] = 0.f;
    float mrun = -1e30f;
    float lr0 = 0.f, lr1 = 0.f;

    const __half* kbase = g_kh + bh * SS * 64;
    const __half* vbase = g_vh + bh * SS * 64;
    const int wbase = i0 + wid * 16;
    const int irelA = wbase + lr;
    const int irelB = irelA + 8;

    auto issue_tile = [&](int ti) {
        const int pbase = (ti == 0) ? 0 : bandlo + (ti - 1) * 64;
        const uint32_t kdst = sbase + (uint32_t)((ti % 3) * ST_KV);
        const uint32_t vdst = kdst + 9216;
#pragma unroll
        for (int i = 0; i < 4; i++) {
            int li = i * 256 + tid;
            int op = li >> 9;
            int rem = li & 511;
            int row = rem >> 3, ch = rem & 7;
            int p = pbase + row;
            p = (p < 0) ? 0 : ((p >= SS) ? SS - 1 : p);
            const __half* src = (op ? vbase : kbase) + (size_t)p * 64 + ch * 8;
            uint32_t dst = (op ? vdst : kdst) + (uint32_t)(row * (KSTR * 2) + ch * 16);
            CP_ASYNC16(dst, src);
        }
        CP_COMMIT();
    };

    issue_tile(0);
    issue_tile(1);

    for (int ti = 0; ti < 11; ti++) {
        CP_WAIT(1);
        __syncthreads();
        if (ti + 2 < 11) issue_tile(ti + 2);

        const uint32_t kbuf = sbase + (uint32_t)((ti % 3) * ST_KV);
        const uint32_t vbuf = kbuf + 9216;

        // S = Q K^T
        float cs[8][4];
#pragma unroll
        for (int nt = 0; nt < 8; nt++)
#pragma unroll
            for (int e = 0; e < 4; e++) cs[nt][e] = 0.f;
#pragma unroll
        for (int kk = 0; kk < 4; kk++) {
#pragma unroll
            for (int g4 = 0; g4 < 4; g4++) {
                uint32_t r0, r1, r2, r3;
                int key = g4 * 16 + l8 + lb * 8;
                int dim = kk * 16 + lh * 8;
                LDSM_X4(r0, r1, r2, r3, kbuf + (uint32_t)(key * (KSTR * 2) + dim * 2));
                MMA_F16(cs[2 * g4],     qa[kk], r0, r2);
                MMA_F16(cs[2 * g4 + 1], qa[kk], r1, r3);
            }
        }

        // masking — boundary/unclean tiles only (warp-uniform test)
        if (ti > 0) {
            const int jbase = (tlo + ti - 1) * 64;
            const bool interior = (tclean[ti - 1] != 0) &&
                                  (jbase >= wbase + 15) &&
                                  (jbase + 63 <= wbase + 2 * WW);
            if (!interior) {
                const unsigned char* okp = okarr + 64 + (ti - 1) * 64;
#pragma unroll
                for (int nt = 0; nt < 8; nt++) {
                    int jl = nt * 8 + 2 * lc;
                    int j = jbase + jl;
                    bool o0 = okp[jl] != 0, o1 = okp[jl + 1] != 0;
                    if (!(o0 && j     >= irelA && j     <= irelA + 512)) cs[nt][0] = -1e30f;
                    if (!(o1 && j + 1 >= irelA && j + 1 <= irelA + 512)) cs[nt][1] = -1e30f;
                    if (!(o0 && j     >= irelB && j     <= irelB + 512)) cs[nt][2] = -1e30f;
                    if (!(o1 && j + 1 >= irelB && j + 1 <= irelB + 512)) cs[nt][3] = -1e30f;
                }
            }
        }

        // warp-uniform online max; rescale only when it moves
        float ml = -1e30f;
#pragma unroll
        for (int nt = 0; nt < 8; nt++)
            ml = fmaxf(ml, fmaxf(fmaxf(cs[nt][0], cs[nt][1]), fmaxf(cs[nt][2], cs[nt][3])));
        ml = fmaxf(ml, __shfl_xor_sync(0xffffffffu, ml, 1));
        ml = fmaxf(ml, __shfl_xor_sync(0xffffffffu, ml, 2));
        ml = fmaxf(ml, __shfl_xor_sync(0xffffffffu, ml, 4));
        ml = fmaxf(ml, __shfl_xor_sync(0xffffffffu, ml, 8));
        ml = fmaxf(ml, __shfl_xor_sync(0xffffffffu, ml, 16));
        if (ml > mrun) {
            float corr = fexp2(mrun - ml);
            mrun = ml;
            lr0 *= corr; lr1 *= corr;
#pragma unroll
            for (int nt = 0; nt < 8; nt++) {
                o[nt][0] *= corr; o[nt][1] *= corr;
                o[nt][2] *= corr; o[nt][3] *= corr;
            }
        }
        float ps0 = 0.f, ps1 = 0.f;
        uint32_t pa[4][4];
#pragma unroll
        for (int nt = 0; nt < 8; nt++) {
            float p0 = fexp2(cs[nt][0] - mrun);
            float p1 = fexp2(cs[nt][1] - mrun);
            float p2 = fexp2(cs[nt][2] - mrun);
            float p3 = fexp2(cs[nt][3] - mrun);
            ps0 += p0 + p1; ps1 += p2 + p3;
            pa[nt >> 1][(nt & 1) * 2 + 0] = packh2(p0, p1);
            pa[nt >> 1][(nt & 1) * 2 + 1] = packh2(p2, p3);
        }
        lr0 += ps0; lr1 += ps1;

        // O += P V
#pragma unroll
        for (int kk = 0; kk < 4; kk++) {
#pragma unroll
            for (int g4 = 0; g4 < 4; g4++) {
                uint32_t r0, r1, r2, r3;
                int key = kk * 16 + l8 + lb * 8;
                int dim = g4 * 16 + lh * 8;
                LDSM_X4_T(r0, r1, r2, r3, vbuf + (uint32_t)(key * (KSTR * 2) + dim * 2));
                MMA_F16(o[2 * g4],     pa[kk], r0, r1);
                MMA_F16(o[2 * g4 + 1], pa[kk], r2, r3);
            }
        }
    }

    // normalize + write directly to row-major g_xatth
#pragma unroll
    for (int e = 0; e < 2; e++) {
        float ll = e ? lr1 : lr0;
        ll += __shfl_xor_sync(0xffffffffu, ll, 1);
        ll += __shfl_xor_sync(0xffffffffu, ll, 2);
        const float inv = 1.f / ll;
        const int srow = s0 + wid * 16 + lr + 8 * e;
        __half* orow = g_xatth + ((size_t)b * SS + srow) * DD + h * 64;
#pragma unroll
        for (int nt = 0; nt < 8; nt++)
            *(uint32_t*)&orow[nt * 8 + 2 * lc] =
                packh2(o[nt][2 * e] * inv, o[nt][2 * e + 1] * inv);
    }
}

__device__ void gattn_body(char* sm, const int* __restrict__ mask)
{
    __half* kgs = (__half*)sm;
    __half* vgs = (__half*)(sm + ST_KV);
    unsigned char* okg = (unsigned char*)(sm + 2 * ST_KV);

    const int split = blockIdx.x - 32, h = blockIdx.y, b = blockIdx.z;
    const int tid = threadIdx.x, wid = tid >> 5, lane = tid & 31;
    const int lr = lane >> 2, lc = lane & 3;
    const int l8 = lane & 7, lb = (lane >> 3) & 1, lh = lane >> 4;
    const size_t bh = (size_t)b * HH + h;
    const int wr = wid & 3, kh = wid >> 2;
    const int p0 = split * 128;

    {
        const __half* kb2 = g_kgh + (bh * SS + p0) * 64;
        const __half* vb2 = g_vgh + (bh * SS + p0) * 64;
        const uint32_t kdst = smem_u32(kgs);
        const uint32_t vdst = smem_u32(vgs);
#pragma unroll
        for (int i = 0; i < 8; i++) {
            int li = i * 256 + tid;
            int op = li >> 10;
            int rem = li & 1023;
            int row = rem >> 3, ch = rem & 7;
            const __half* src = (op ? vb2 : kb2) + (size_t)row * 64 + ch * 8;
            uint32_t dst = (op ? vdst : kdst) + (uint32_t)(row * (KSTR * 2) + ch * 16);
            CP_ASYNC16(dst, src);
        }
        CP_COMMIT();
        if (tid < 128) okg[tid] = (mask[b * SS + p0 + tid] <= 0) ? 1 : 0;
        CP_WAIT(0);
        __syncthreads();
    }

    uint32_t qa[4][4];
    {
        const __half* qb2 = g_qgh + (bh * GG + wr * 16) * 64;
#pragma unroll
        for (int kk = 0; kk < 4; kk++) {
            qa[kk][0] = *(const uint32_t*)&qb2[(lr)     * 64 + kk * 16 + 2 * lc];
            qa[kk][1] = *(const uint32_t*)&qb2[(lr + 8) * 64 + kk * 16 + 2 * lc];
            qa[kk][2] = *(const uint32_t*)&qb2[(lr)     * 64 + kk * 16 + 8 + 2 * lc];
            qa[kk][3] = *(const uint32_t*)&qb2[(lr + 8) * 64 + kk * 16 + 8 + 2 * lc];
        }
    }

    const uint32_t kbuf = smem_u32(kgs) + (uint32_t)(kh * 64 * KSTR * 2);
    const uint32_t vbuf = smem_u32(vgs) + (uint32_t)(kh * 64 * KSTR * 2);

    float cs[8][4];
#pragma unroll
    for (int nt = 0; nt < 8; nt++)
#pragma unroll
        for (int e = 0; e < 4; e++) cs[nt][e] = 0.f;
#pragma unroll
    for (int kk = 0; kk < 4; kk++) {
#pragma unroll
        for (int g4 = 0; g4 < 4; g4++) {
            uint32_t r0, r1, r2, r3;
            int key = g4 * 16 + l8 + lb * 8;
            int dim = kk * 16 + lh * 8;
            LDSM_X4(r0, r1, r2, r3, kbuf + (uint32_t)(key * (KSTR * 2) + dim * 2));
            MMA_F16(cs[2 * g4],     qa[kk], r0, r2);
            MMA_F16(cs[2 * g4 + 1], qa[kk], r1, r3);
        }
    }
#pragma unroll
    for (int nt = 0; nt < 8; nt++) {
        int jl = kh * 64 + nt * 8 + 2 * lc;
        if (!okg[jl])     { cs[nt][0] = -1e30f; cs[nt][2] = -1e30f; }
        if (!okg[jl + 1]) { cs[nt][1] = -1e30f; cs[nt][3] = -1e30f; }
    }
    float ml0 = -1e30f, ml1 = -1e30f;
#pragma unroll
    for (int nt = 0; nt < 8; nt++) {
        ml0 = fmaxf(ml0, fmaxf(cs[nt][0], cs[nt][1]));
        ml1 = fmaxf(ml1, fmaxf(cs[nt][2], cs[nt][3]));
    }
    ml0 = fmaxf(ml0, __shfl_xor_sync(0xffffffffu, ml0, 1));
    ml0 = fmaxf(ml0, __shfl_xor_sync(0xffffffffu, ml0, 2));
    ml1 = fmaxf(ml1, __shfl_xor_sync(0xffffffffu, ml1, 1));
    ml1 = fmaxf(ml1, __shfl_xor_sync(0xffffffffu, ml1, 2));
    float ps0 = 0.f, ps1 = 0.f;
    uint32_t pa[4][4];
#pragma unroll
    for (int nt = 0; nt < 8; nt++) {
        float pp0 = fexp2(cs[nt][0] - ml0);
        float pp1 = fexp2(cs[nt][1] - ml0);
        float pp2 = fexp2(cs[nt][2] - ml1);
        float pp3 = fexp2(cs[nt][3] - ml1);
        ps0 += pp0 + pp1; ps1 += pp2 + pp3;
        pa[nt >> 1][(nt & 1) * 2 + 0] = packh2(pp0, pp1);
        pa[nt >> 1][(nt & 1) * 2 + 1] = packh2(pp2, pp3);
    }
    ps0 += __shfl_xor_sync(0xffffffffu, ps0, 1);
    ps0 += __shfl_xor_sync(0xffffffffu, ps0, 2);
    ps1 += __shfl_xor_sync(0xffffffffu, ps1, 1);
    ps1 += __shfl_xor_sync(0xffffffffu, ps1, 2);

    float o[8][4];
#pragma unroll
    for (int nt = 0; nt < 8; nt++)
#pragma unroll
        for (int e = 0; e < 4; e++) o[nt][e] = 0.f;
#pragma unroll
    for (int kk = 0; kk < 4; kk++) {
#pragma unroll
        for (int g4 = 0; g4 < 4; g4++) {
            uint32_t r0, r1, r2, r3;
            int key = kk * 16 + l8 + lb * 8;
            int dim = g4 * 16 + lh * 8;
            LDSM_X4_T(r0, r1, r2, r3, vbuf + (uint32_t)(key * (KSTR * 2) + dim * 2));
            MMA_F16(o[2 * g4],     pa[kk], r0, r1);
            MMA_F16(o[2 * g4 + 1], pa[kk], r2, r3);
        }
    }

    const int pid = split * 2 + kh;
#pragma unroll
    for (int e = 0; e < 2; e++) {
        const int grow = wr * 16 + lr + 8 * e;
        const size_t idx = (bh * GG + grow) * 64 + pid;
        if (lc == 0) {
            g_pm[idx] = e ? ml1 : ml0;
            g_pl[idx] = e ? ps1 : ps0;
        }
        float* ap = g_pacc + idx * 64;
#pragma unroll
        for (int nt = 0; nt < 8; nt++)
            *(float2*)&ap[nt * 8 + 2 * lc] = make_float2(o[nt][2 * e], o[nt][2 * e + 1]);
    }
}

__global__ __launch_bounds__(256, 2)
void attn_merged(const int* __restrict__ mask)
{
    extern __shared__ char sm[];
    if (blockIdx.x < 32) local_attn_body(sm, mask);
    else                 gattn_body(sm, mask);
}

__global__ void gattn_combine_kernel(void)
{
    const int rid = blockIdx.x * blockDim.x + threadIdx.x;
    if (rid >= BB * HH * GG) return;
    float M = -1e30f;
    for (int p = 0; p < 64; p++) M = fmaxf(M, g_pm[(size_t)rid * 64 + p]);
    float L = 0.f;
    float acc[64];
#pragma unroll
    for (int d = 0; d < 64; d++) acc[d] = 0.f;
    for (int p = 0; p < 64; p++) {
        const float w = fexp2(g_pm[(size_t)rid * 64 + p] - M);
        L += g_pl[(size_t)rid * 64 + p] * w;
        const float* ap = g_pacc + ((size_t)rid * 64 + p) * 64;
#pragma unroll
        for (int d = 0; d < 64; d += 4) {
            float4 a4 = *(const float4*)(ap + d);
            acc[d]   += w * a4.x;
            acc[d+1] += w * a4.y;
            acc[d+2] += w * a4.z;
            acc[d+3] += w * a4.w;
        }
    }
    const float inv = 1.f / L;
    const int bh = rid >> 6, g = rid & 63;
    const int b = bh / HH, h = bh % HH;
    __half* orow = g_xatth + ((size_t)b * SS + g) * DD + h * 64;
#pragma unroll
    for (int d = 0; d < 64; d += 2)
        *(uint32_t*)&orow[d] = packh2(acc[d] * inv, acc[d + 1] * inv);
}

// ---------------- launcher ----------------
extern "C" void kernel_launch(void* const* d_in, const int* in_sizes, int n_in,
                              void* d_out, int out_size)
{
    (void)in_sizes; (void)n_in; (void)out_size;
    const float* query = (const float*)d_in[0];
    const int*   mask  = (const int*)d_in[1];
    const float* Wq  = (const float*)d_in[2];
    const float* bq  = (const float*)d_in[3];
    const float* Wk  = (const float*)d_in[4];
    const float* bk  = (const float*)d_in[5];
    const float* Wv  = (const float*)d_in[6];
    const float* bv  = (const float*)d_in[7];
    const float* Wqg = (const float*)d_in[8];
    const float* bqg = (const float*)d_in[9];
    const float* Wkg = (const float*)d_in[10];
    const float* bkg = (const float*)d_in[11];
    const float* Wvg = (const float*)d_in[12];
    const float* bvg = (const float*)d_in[13];
    const float* Wo  = (const float*)d_in[14];
    const float* bo  = (const float*)d_in[15];
    float* out = (float*)d_out;

    __half *qb, *kb, *vb, *kgb, *vgb, *qgb;
    cudaGetSymbolAddress((void**)&qb,  g_qh);
    cudaGetSymbolAddress((void**)&kb,  g_kh);
    cudaGetSymbolAddress((void**)&vb,  g_vh);
    cudaGetSymbolAddress((void**)&kgb, g_kgh);
    cudaGetSymbolAddress((void**)&vgb, g_vgh);
    cudaGetSymbolAddress((void**)&qgb, g_qgh);

    cudaFuncSetAttribute(mma_gemm6,    cudaFuncAttributeMaxDynamicSharedMemorySize, SMT);
    cudaFuncSetAttribute(mma_gemm_out, cudaFuncAttributeMaxDynamicSharedMemorySize, SMT);
    cudaFuncSetAttribute(attn_merged,  cudaFuncAttributeMaxDynamicSharedMemorySize, LA_SMEM);

    // launches 0,1: weight transposes (split so gemm6 lands in profile slot 3)
    W7 w7;
    w7.w[0] = Wq; w7.w[1] = Wk; w7.w[2] = Wv; w7.w[3] = Wkg;
    w7.w[4] = Wvg; w7.w[5] = Wqg; w7.w[6] = Wo;
    k_wt_all<<<dim3(24, 24, 4), dim3(32, 8)>>>(w7, 0);
    k_wt_all<<<dim3(24, 24, 3), dim3(32, 8)>>>(w7, 4);

    // launch 2: input transpose
    const int ntot = BB * SS * DD;
    k_xin<<<(ntot + 255) / 256, 256>>>(query);

    // launch 3: 6 batched GEMMs (PROFILE SLOT)
    Gemm6 p6;
    p6.bias[0] = bq;  p6.out[0] = qb;  p6.scale[0] = QSCALE;
    p6.bias[1] = bk;  p6.out[1] = kb;  p6.scale[1] = 1.0f;
    p6.bias[2] = bv;  p6.out[2] = vb;  p6.scale[2] = 1.0f;
    p6.bias[3] = bkg; p6.out[3] = kgb; p6.scale[3] = 1.0f;
    p6.bias[4] = bvg; p6.out[4] = vgb; p6.scale[4] = 1.0f;
    p6.bias[5] = bqg; p6.out[5] = qgb; p6.scale[5] = QSCALE;
    mma_gemm6<<<dim3(6, 64, 6), 256, SMT>>>(p6);

    // launch 4: merged local + global attention
    attn_merged<<<dim3(64, HH, BB), 256, LA_SMEM>>>(mask);

    // launch 5: combine global partials
    gattn_combine_kernel<<<(BB * HH * GG + 255) / 256, 256>>>();

    // launch 6: final GEMM
    mma_gemm_out<<<dim3(6, 64), 256, SMT>>>(bo, out);
}